// round 4
// baseline (speedup 1.0000x reference)
#include <cuda_runtime.h>
#include <math.h>
#include <float.h>
#include <stdint.h>

#define TT   4096
#define HD   1024
#define EDN  8
#define NE   9
#define IDY  512
#define IFX  2048
#define CAPV 640
#define TOPK 4
#define TOPP 0.75f
#define JEPS2 0.2f

// ---- mma.sync tf32 GEMM tiling ----
#define BM   128
#define BN   128
#define BK   32
#define BKP  36                                // padded row (floats)
#define NSTG 4
#define STAGE_FLOATS ((BM + BN) * BKP)         // 9216
#define GEMM_SMEM (NSTG * STAGE_FLOATS * 4)    // 147456 B

__device__ __forceinline__ uint32_t smem_u32(const void* p) {
    uint32_t a;
    asm("{ .reg .u64 t; cvta.to.shared.u64 t, %1; cvt.u32.u64 %0, t; }" : "=r"(a) : "l"(p));
    return a;
}
__device__ __forceinline__ void cp_async16(uint32_t dst, const void* src) {
    asm volatile("cp.async.cg.shared.global [%0], [%1], 16;" :: "r"(dst), "l"(src));
}
template<int N> __device__ __forceinline__ void cp_wait() {
    asm volatile("cp.async.wait_group %0;" :: "n"(N) : "memory");
}
__device__ __forceinline__ float rna_tf32(float x) {
    uint32_t u;
    asm("cvt.rna.tf32.f32 %0, %1;" : "=r"(u) : "f"(x));
    return __uint_as_float(u);
}
__device__ __forceinline__ uint32_t rna_tf32_u(float x) {
    uint32_t u;
    asm("cvt.rna.tf32.f32 %0, %1;" : "=r"(u) : "f"(x));
    return u;
}

// ----------------- device scratch (static, no allocations) -----------------
__device__ float d_logits[TT * NE];
__device__ int   d_sel[TT * TOPK];
__device__ float d_rw[TT * TOPK];
__device__ int   d_mask[TT * EDN];
__device__ int   d_kept[TT * EDN];
__device__ int   d_counts[EDN];
__device__ int   d_etok[EDN * CAPV];
__device__ int   d_tokpos[TT * TOPK];
__device__ int   d_toke[TT * TOPK];
__device__ float d_tokw[TT * TOPK];
__device__ float d_wsh[TT];
__device__ float d_xe[(size_t)EDN * CAPV * HD];
__device__ float d_gbuf[(size_t)EDN * CAPV * IDY];
__device__ float d_ubuf[(size_t)EDN * CAPV * IDY];
__device__ float d_hbuf[(size_t)EDN * CAPV * IDY];
__device__ float d_ybuf[(size_t)EDN * CAPV * HD];
__device__ float d_gs[(size_t)TT * IFX];
__device__ float d_us[(size_t)TT * IFX];
__device__ float d_hs[(size_t)TT * IFX];

// ----------------- K1: router logits ---------------------------------------
__global__ __launch_bounds__(256) void logits_kernel(
    const float* __restrict__ x, const float* __restrict__ gw)
{
    int widx = blockIdx.x * 8 + (threadIdx.x >> 5);
    if (widx >= TT * NE) return;
    int t = widx / NE, e = widx - t * NE;
    int lane = threadIdx.x & 31;
    const float4* xr = (const float4*)(x + (size_t)t * HD);
    const float4* wr = (const float4*)(gw + (size_t)e * HD);
    float s = 0.f;
#pragma unroll
    for (int i = 0; i < HD / 128; i++) {
        float4 a = xr[lane + i * 32];
        float4 b = wr[lane + i * 32];
        s += a.x * b.x + a.y * b.y + a.z * b.z + a.w * b.w;
    }
#pragma unroll
    for (int o = 16; o; o >>= 1) s += __shfl_xor_sync(0xffffffffu, s, o);
    if (!lane) d_logits[widx] = s;
}

// ----------------- K2: per-token routing ------------------------------------
__global__ void routing_kernel()
{
    int t = blockIdx.x * blockDim.x + threadIdx.x;
    if (t >= TT) return;

    float s[EDN];
#pragma unroll
    for (int e = 0; e < EDN; e++) s[e] = d_logits[t * NE + e];

    float m = s[0];
#pragma unroll
    for (int e = 1; e < EDN; e++) m = fmaxf(m, s[e]);
    float p[EDN]; float den = 0.f;
#pragma unroll
    for (int e = 0; e < EDN; e++) { p[e] = expf(s[e] - m); den += p[e]; }
#pragma unroll
    for (int e = 0; e < EDN; e++) p[e] /= den;
    float sp[EDN];
#pragma unroll
    for (int e = 0; e < EDN; e++) sp[e] = p[e];
    for (int i = 1; i < EDN; i++) {
        float v = sp[i]; int j = i - 1;
        while (j >= 0 && sp[j] < v) { sp[j + 1] = sp[j]; j--; }
        sp[j + 1] = v;
    }
    float c = 0.f; int cnt = 0;
#pragma unroll
    for (int e = 0; e < EDN; e++) { c += sp[e]; if (c < TOPP) cnt++; }
    int dyn_k = min(cnt + 1, TOPK);

    float masked[EDN];
#pragma unroll
    for (int e = 0; e < EDN; e++) masked[e] = s[e];
    float mult[TOPK]; int sel[TOPK];
    for (int k = 0; k < TOPK; k++) {
        float thr = masked[0]; int sl = 0;
        for (int e = 1; e < EDN; e++)
            if (masked[e] > thr) { thr = masked[e]; sl = e; }
        bool keep[EDN];
        float gm = -INFINITY;
        for (int e = 0; e < EDN; e++) {
            float fac = fmaxf(fabsf(s[e]), fabsf(thr));
            float jm = (thr - s[e]) / fac;
            keep[e] = !(jm > JEPS2);
            if (keep[e]) gm = fmaxf(gm, masked[e]);
        }
        float d2 = 0.f;
        for (int e = 0; e < EDN; e++)
            if (keep[e]) d2 += expf(masked[e] - gm);
        mult[k] = expf(thr - gm) / d2;
        sel[k] = sl;
        masked[sl] = -INFINITY;
    }
    float rsum = 0.f;
#pragma unroll
    for (int k = 0; k < TOPK; k++) {
        if (k >= dyn_k) mult[k] = 0.f;
        rsum += mult[k];
    }
    int mk[EDN];
#pragma unroll
    for (int e = 0; e < EDN; e++) mk[e] = 0;
#pragma unroll
    for (int k = 0; k < TOPK; k++) {
        float r = mult[k] / rsum;
        d_rw[t * TOPK + k] = r;
        d_sel[t * TOPK + k] = sel[k];
        if (mult[k] > 0.f) mk[sel[k]] = 1;
    }
#pragma unroll
    for (int e = 0; e < EDN; e++) d_mask[t * EDN + e] = mk[e];
}

// ----------------- K3: capacity scan (warp-ballot, 1 CTA, 8 warps) ----------
__global__ __launch_bounds__(256) void scan_kernel()
{
    int w = threadIdx.x >> 5;      // expert id
    int lane = threadIdx.x & 31;
    if (threadIdx.x < EDN) d_counts[threadIdx.x] = 0;
    int carry = 0;
    for (int c0 = 0; c0 < TT / 256; c0++) {      // 16 outer iters
        int v[8];
#pragma unroll
        for (int j = 0; j < 8; j++) {
            int t = c0 * 256 + j * 32 + lane;
            v[j] = d_mask[t * EDN + w];
        }
#pragma unroll
        for (int j = 0; j < 8; j++) {
            unsigned bal = __ballot_sync(0xffffffffu, v[j]);
            int pre = __popc(bal & ((1u << lane) - 1));
            int incl = carry + pre + v[j];
            int t = c0 * 256 + j * 32 + lane;
            d_kept[t * EDN + w] = (v[j] && incl <= CAPV) ? 1 : 0;
            carry += __popc(bal);
        }
    }
}

// ----------------- K4: masked softmax + compaction --------------------------
__global__ void finalize_kernel()
{
    int t = blockIdx.x * blockDim.x + threadIdx.x;
    if (t >= TT) return;
    float l[NE];
#pragma unroll
    for (int i = 0; i < NE; i++) l[i] = d_logits[t * NE + i];
    int km[EDN];
#pragma unroll
    for (int e = 0; e < EDN; e++) km[e] = d_kept[t * EDN + e];

    float m = l[EDN];
#pragma unroll
    for (int e = 0; e < EDN; e++) if (km[e]) m = fmaxf(m, l[e]);
    float den = 0.f, dynsum = 0.f;
#pragma unroll
    for (int e = 0; e < EDN; e++)
        if (km[e]) { float ex = expf(l[e] - m); den += ex; dynsum += ex; }
    float exsh = expf(l[EDN] - m);
    den += exsh;
    d_wsh[t] = exsh / den;
    float sumdyn = dynsum / den;

#pragma unroll
    for (int k = 0; k < TOPK; k++) {
        float r = d_rw[t * TOPK + k];
        int e = d_sel[t * TOPK + k];
        int pos = -1;
        if (r > 0.f && km[e]) {
            pos = atomicAdd(&d_counts[e], 1);
            d_etok[e * CAPV + pos] = t;
            d_toke[t * TOPK + k] = e;
            d_tokw[t * TOPK + k] = r * sumdyn;
        }
        d_tokpos[t * TOPK + k] = pos;
    }
}

// ----------------- K5: gather x rows per expert (tf32-rounded) --------------
__global__ __launch_bounds__(256) void gather_kernel(const float* __restrict__ x)
{
    int b = blockIdx.x;
    int e = b / CAPV, i = b - e * CAPV;
    int c = threadIdx.x;
    float4* dst = (float4*)(d_xe + ((size_t)e * CAPV + i) * HD);
    if (i < d_counts[e]) {
        int t = d_etok[e * CAPV + i];
        float4 v = ((const float4*)(x + (size_t)t * HD))[c];
        v.x = rna_tf32(v.x); v.y = rna_tf32(v.y);
        v.z = rna_tf32(v.z); v.w = rna_tf32(v.w);
        dst[c] = v;
    } else {
        dst[c] = make_float4(0.f, 0.f, 0.f, 0.f);
    }
}

// ----------------- mma.sync tf32 GEMM: C[M,N] = A[M,K] @ B[N,K]^T -----------
// 128x128x32 CTA tile, 8 warps (2x4), warp tile 64x32, m16n8k8 tf32 MMA,
// 4-stage cp.async pipeline. Fragments rounded to tf32 (rna) at load —
// numerically identical to pre-rounded inputs. z < zSplit -> (Ba,Ca) else
// (Bb,Cb). mode=1: scale row r of C by rs[r].
__global__ __launch_bounds__(256, 1) void tf32_gemm_kernel(
    const float* __restrict__ A,
    const float* __restrict__ Ba, const float* __restrict__ Bb,
    float* __restrict__ Ca, float* __restrict__ Cb,
    int K, int N, size_t strA, size_t strB, size_t strC,
    int zSplit, int mode, const float* __restrict__ rs)
{
    extern __shared__ float smem[];
    int tid = threadIdx.x;
    int w = tid >> 5, lane = tid & 31;
    int wm = w >> 2, wn = w & 3;          // 2 x 4 warp grid
    int grp = lane >> 2, tig = lane & 3;  // mma fragment coords

    int z = blockIdx.z;
    const float* Bp; float* Cp; int e;
    if (z < zSplit) { e = z; Bp = Ba; Cp = Ca; }
    else            { e = z - zSplit; Bp = Bb; Cp = Cb; }
    const float* Ap = A + (size_t)e * strA + (size_t)blockIdx.y * BM * K;
    Bp += (size_t)e * strB + (size_t)blockIdx.x * BN * K;
    Cp += (size_t)e * strC;

    float acc[4][4][4] = {};
    int KT = K / BK;

    // prologue: stages 0..NSTG-2
#pragma unroll
    for (int pt = 0; pt < NSTG - 1; pt++) {
        float* dstA = smem + pt * STAGE_FLOATS;
        float* dstB = dstA + BM * BKP;
#pragma unroll
        for (int i = 0; i < 4; i++) {
            int idx = tid + i * 256, row = idx >> 3, c = idx & 7;
            cp_async16(smem_u32(dstA + row * BKP + c * 4),
                       Ap + (size_t)row * K + pt * BK + c * 4);
        }
#pragma unroll
        for (int i = 0; i < 4; i++) {
            int idx = tid + i * 256, row = idx >> 3, c = idx & 7;
            cp_async16(smem_u32(dstB + row * BKP + c * 4),
                       Bp + (size_t)row * K + pt * BK + c * 4);
        }
        asm volatile("cp.async.commit_group;" ::: "memory");
    }

    for (int kt = 0; kt < KT; kt++) {
        cp_wait<NSTG - 2>();
        __syncthreads();
        const float* As = smem + (kt % NSTG) * STAGE_FLOATS;
        const float* Bs = As + BM * BKP;

#pragma unroll
        for (int k8 = 0; k8 < BK / 8; k8++) {
            int k0 = k8 * 8;
            uint32_t af[4][4], bf[4][2];
#pragma unroll
            for (int mf = 0; mf < 4; mf++) {
                const float* p = As + (wm * 64 + mf * 16 + grp) * BKP + k0 + tig;
                af[mf][0] = rna_tf32_u(p[0]);
                af[mf][1] = rna_tf32_u(p[8 * BKP]);
                af[mf][2] = rna_tf32_u(p[4]);
                af[mf][3] = rna_tf32_u(p[8 * BKP + 4]);
            }
#pragma unroll
            for (int nf = 0; nf < 4; nf++) {
                const float* p = Bs + (wn * 32 + nf * 8 + grp) * BKP + k0 + tig;
                bf[nf][0] = rna_tf32_u(p[0]);
                bf[nf][1] = rna_tf32_u(p[4]);
            }
#pragma unroll
            for (int mf = 0; mf < 4; mf++)
#pragma unroll
                for (int nf = 0; nf < 4; nf++)
                    asm volatile(
                        "mma.sync.aligned.m16n8k8.row.col.f32.tf32.tf32.f32 "
                        "{%0,%1,%2,%3}, {%4,%5,%6,%7}, {%8,%9}, {%0,%1,%2,%3};"
                        : "+f"(acc[mf][nf][0]), "+f"(acc[mf][nf][1]),
                          "+f"(acc[mf][nf][2]), "+f"(acc[mf][nf][3])
                        : "r"(af[mf][0]), "r"(af[mf][1]),
                          "r"(af[mf][2]), "r"(af[mf][3]),
                          "r"(bf[nf][0]), "r"(bf[nf][1]));
        }
        __syncthreads();

        int lt = kt + NSTG - 1;
        if (lt < KT) {
            float* dstA = smem + (lt % NSTG) * STAGE_FLOATS;
            float* dstB = dstA + BM * BKP;
#pragma unroll
            for (int i = 0; i < 4; i++) {
                int idx = tid + i * 256, row = idx >> 3, c = idx & 7;
                cp_async16(smem_u32(dstA + row * BKP + c * 4),
                           Ap + (size_t)row * K + lt * BK + c * 4);
            }
#pragma unroll
            for (int i = 0; i < 4; i++) {
                int idx = tid + i * 256, row = idx >> 3, c = idx & 7;
                cp_async16(smem_u32(dstB + row * BKP + c * 4),
                           Bp + (size_t)row * K + lt * BK + c * 4);
            }
            asm volatile("cp.async.commit_group;" ::: "memory");
        }
    }

    // epilogue
    int rowBase = blockIdx.y * BM, colBase = blockIdx.x * BN;
#pragma unroll
    for (int mf = 0; mf < 4; mf++) {
        int r0 = rowBase + wm * 64 + mf * 16 + grp;
        float s0 = mode ? rs[r0] : 1.f;
        float s1 = mode ? rs[r0 + 8] : 1.f;
#pragma unroll
        for (int nf = 0; nf < 4; nf++) {
            int col = colBase + wn * 32 + nf * 8 + tig * 2;
            float2 v0 = { acc[mf][nf][0] * s0, acc[mf][nf][1] * s0 };
            float2 v1 = { acc[mf][nf][2] * s1, acc[mf][nf][3] * s1 };
            *(float2*)(Cp + (size_t)r0 * N + col) = v0;
            *(float2*)(Cp + (size_t)(r0 + 8) * N + col) = v1;
        }
    }
}

// ----------------- silu(g)*u elementwise, rounded to tf32 -------------------
__global__ __launch_bounds__(256) void silu_mul_kernel(
    const float* __restrict__ g, const float* __restrict__ u,
    float* __restrict__ h, int n4)
{
    int i = blockIdx.x * blockDim.x + threadIdx.x;
    if (i >= n4) return;
    float4 gv = ((const float4*)g)[i];
    float4 uv = ((const float4*)u)[i];
    float4 r;
    r.x = rna_tf32(gv.x / (1.f + expf(-gv.x)) * uv.x);
    r.y = rna_tf32(gv.y / (1.f + expf(-gv.y)) * uv.y);
    r.z = rna_tf32(gv.z / (1.f + expf(-gv.z)) * uv.z);
    r.w = rna_tf32(gv.w / (1.f + expf(-gv.w)) * uv.w);
    ((float4*)h)[i] = r;
}

// ----------------- combine dyn expert outputs into out ----------------------
__global__ __launch_bounds__(256) void combine_kernel(float* __restrict__ out)
{
    int t = blockIdx.x;
    int c = threadIdx.x;
    float4 acc = ((float4*)(out + (size_t)t * HD))[c];
#pragma unroll
    for (int k = 0; k < TOPK; k++) {
        int pos = d_tokpos[t * TOPK + k];
        if (pos >= 0) {
            int e = d_toke[t * TOPK + k];
            float w = d_tokw[t * TOPK + k];
            float4 v = ((const float4*)(d_ybuf + ((size_t)e * CAPV + pos) * HD))[c];
            acc.x += w * v.x; acc.y += w * v.y;
            acc.z += w * v.z; acc.w += w * v.w;
        }
    }
    ((float4*)(out + (size_t)t * HD))[c] = acc;
}

// ----------------- host launcher --------------------------------------------
extern "C" void kernel_launch(void* const* d_in, const int* in_sizes, int n_in,
                              void* d_out, int out_size)
{
    const float* x   = (const float*)d_in[0];
    const float* gw  = (const float*)d_in[1];
    const float* dgw = (const float*)d_in[2];
    const float* duw = (const float*)d_in[3];
    const float* ddw = (const float*)d_in[4];
    const float* sgw = (const float*)d_in[5];
    const float* suw = (const float*)d_in[6];
    const float* sdw = (const float*)d_in[7];
    float* out = (float*)d_out;

    float *p_xe, *p_g, *p_u, *p_h, *p_y, *p_gs, *p_us, *p_hs, *p_wsh;
    cudaGetSymbolAddress((void**)&p_xe, d_xe);
    cudaGetSymbolAddress((void**)&p_g, d_gbuf);
    cudaGetSymbolAddress((void**)&p_u, d_ubuf);
    cudaGetSymbolAddress((void**)&p_h, d_hbuf);
    cudaGetSymbolAddress((void**)&p_y, d_ybuf);
    cudaGetSymbolAddress((void**)&p_gs, d_gs);
    cudaGetSymbolAddress((void**)&p_us, d_us);
    cudaGetSymbolAddress((void**)&p_hs, d_hs);
    cudaGetSymbolAddress((void**)&p_wsh, d_wsh);

    cudaFuncSetAttribute(tf32_gemm_kernel,
                         cudaFuncAttributeMaxDynamicSharedMemorySize, GEMM_SMEM);

    // launch idx:  0..4 routing chain, 5 = shared gate+up GEMM (ncu -s 5 target)
    logits_kernel<<<(TT * NE + 7) / 8, 256>>>(x, gw);          // 0
    routing_kernel<<<(TT + 255) / 256, 256>>>();               // 1
    scan_kernel<<<1, 256>>>();                                 // 2
    finalize_kernel<<<(TT + 255) / 256, 256>>>();              // 3
    gather_kernel<<<EDN * CAPV, 256>>>(x);                     // 4

    // shared expert gate+up: A = x (rounded in-fragment), z=0 gate, z=1 up
    dim3 gs1(IFX / BN, TT / BM, 2);
    tf32_gemm_kernel<<<gs1, 256, GEMM_SMEM>>>(                 // 5  <- profiled
        x, sgw, suw, p_gs, p_us, HD, IFX, 0, 0, 0, 1, 0, nullptr);

    // dyn experts gate+up (z<8: gate, z>=8: up)
    dim3 gd1(IDY / BN, CAPV / BM, 2 * EDN);
    tf32_gemm_kernel<<<gd1, 256, GEMM_SMEM>>>(                 // 6
        p_xe, dgw, duw, p_g, p_u, HD, IDY,
        (size_t)CAPV * HD, (size_t)IDY * HD, (size_t)CAPV * IDY, EDN, 0, nullptr);
    int n4d = EDN * CAPV * IDY / 4;
    silu_mul_kernel<<<(n4d + 255) / 256, 256>>>(p_g, p_u, p_h, n4d);   // 7
    dim3 gd2(HD / BN, CAPV / BM, EDN);
    tf32_gemm_kernel<<<gd2, 256, GEMM_SMEM>>>(                 // 8
        p_h, ddw, nullptr, p_y, nullptr, IDY, HD,
        (size_t)CAPV * IDY, (size_t)HD * IDY, (size_t)CAPV * HD, EDN, 0, nullptr);

    // shared expert silu + down (scaled by softmax weight, writes out)
    int n4s = TT * IFX / 4;
    silu_mul_kernel<<<(n4s + 255) / 256, 256>>>(p_gs, p_us, p_hs, n4s); // 9
    dim3 gs2(HD / BN, TT / BM, 1);
    tf32_gemm_kernel<<<gs2, 256, GEMM_SMEM>>>(                 // 10
        p_hs, sdw, nullptr, out, nullptr, IFX, HD, 0, 0, 0, 1, 1, p_wsh);

    // add dyn contributions
    combine_kernel<<<TT, 256>>>(out);                          // 11
}

// round 5
// speedup vs baseline: 1.0188x; 1.0188x over previous
#include <cuda_runtime.h>
#include <math.h>
#include <float.h>
#include <stdint.h>

#define TT   4096
#define HD   1024
#define EDN  8
#define NE   9
#define IDY  512
#define IFX  2048
#define CAPV 640
#define TOPK 4
#define TOPP 0.75f
#define JEPS2 0.2f

// ---- mma.sync tf32 GEMM tiling: CTA 128x256x32, 8 warps (2x4), warp 64x64 --
#define BM   128
#define BN   256
#define BK   32
#define BKP  36                                // padded row (floats)
#define NSTG 4
#define STAGE_FLOATS ((BM + BN) * BKP)         // 13824
#define GEMM_SMEM (NSTG * STAGE_FLOATS * 4)    // 221184 B

__device__ __forceinline__ uint32_t smem_u32(const void* p) {
    uint32_t a;
    asm("{ .reg .u64 t; cvta.to.shared.u64 t, %1; cvt.u32.u64 %0, t; }" : "=r"(a) : "l"(p));
    return a;
}
__device__ __forceinline__ void cp_async16(uint32_t dst, const void* src) {
    asm volatile("cp.async.cg.shared.global [%0], [%1], 16;" :: "r"(dst), "l"(src));
}
template<int N> __device__ __forceinline__ void cp_wait() {
    asm volatile("cp.async.wait_group %0;" :: "n"(N) : "memory");
}
__device__ __forceinline__ float rna_tf32(float x) {
    uint32_t u;
    asm("cvt.rna.tf32.f32 %0, %1;" : "=r"(u) : "f"(x));
    return __uint_as_float(u);
}

// ----------------- device scratch (static, no allocations) -----------------
__device__ float d_logits[TT * NE];
__device__ int   d_sel[TT * TOPK];
__device__ float d_rw[TT * TOPK];
__device__ int   d_mask[TT * EDN];
__device__ int   d_kept[TT * EDN];
__device__ int   d_counts[EDN];
__device__ int   d_etok[EDN * CAPV];
__device__ int   d_tokpos[TT * TOPK];
__device__ int   d_toke[TT * TOPK];
__device__ float d_tokw[TT * TOPK];
__device__ float d_wsh[TT];
__device__ float d_xe[(size_t)EDN * CAPV * HD];
__device__ float d_gbuf[(size_t)EDN * CAPV * IDY];
__device__ float d_ubuf[(size_t)EDN * CAPV * IDY];
__device__ float d_hbuf[(size_t)EDN * CAPV * IDY];
__device__ float d_ybuf[(size_t)EDN * CAPV * HD];
__device__ float d_gs[(size_t)TT * IFX];
__device__ float d_us[(size_t)TT * IFX];
__device__ float d_hs[(size_t)TT * IFX];
// tf32-rounded copies
__device__ float d_xr[(size_t)TT * HD];
__device__ float d_dgw_r[(size_t)EDN * IDY * HD];
__device__ float d_duw_r[(size_t)EDN * IDY * HD];
__device__ float d_ddw_r[(size_t)EDN * HD * IDY];
__device__ float d_sgw_r[(size_t)IFX * HD];
__device__ float d_suw_r[(size_t)IFX * HD];
__device__ float d_sdw_r[(size_t)HD * IFX];

// ----------------- K0: segmented round-to-tf32 prepass (one launch) ---------
// seg sizes in float4 units
#define SEG_DW (EDN * IDY * HD / 4)     // 1048576
#define SEG_SW (IFX * HD / 4)           // 524288
#define SEG_X  (TT * HD / 4)            // 1048576
__global__ __launch_bounds__(256) void round_all_kernel(
    const float4* __restrict__ dgw, const float4* __restrict__ duw,
    const float4* __restrict__ ddw, const float4* __restrict__ sgw,
    const float4* __restrict__ suw, const float4* __restrict__ sdw,
    const float4* __restrict__ x)
{
    long i = (long)blockIdx.x * blockDim.x + threadIdx.x;
    const float4* src; float4* dst; long off;
    if (i < SEG_DW)            { src = dgw; dst = (float4*)d_dgw_r; off = i; }
    else if (i < 2L*SEG_DW)    { src = duw; dst = (float4*)d_duw_r; off = i - SEG_DW; }
    else if (i < 3L*SEG_DW)    { src = ddw; dst = (float4*)d_ddw_r; off = i - 2L*SEG_DW; }
    else if (i < 3L*SEG_DW + SEG_SW)   { src = sgw; dst = (float4*)d_sgw_r; off = i - 3L*SEG_DW; }
    else if (i < 3L*SEG_DW + 2L*SEG_SW){ src = suw; dst = (float4*)d_suw_r; off = i - 3L*SEG_DW - SEG_SW; }
    else if (i < 3L*SEG_DW + 3L*SEG_SW){ src = sdw; dst = (float4*)d_sdw_r; off = i - 3L*SEG_DW - 2L*SEG_SW; }
    else if (i < 3L*SEG_DW + 3L*SEG_SW + SEG_X)
                               { src = x;   dst = (float4*)d_xr;    off = i - 3L*SEG_DW - 3L*SEG_SW; }
    else return;
    float4 v = src[off];
    v.x = rna_tf32(v.x); v.y = rna_tf32(v.y);
    v.z = rna_tf32(v.z); v.w = rna_tf32(v.w);
    dst[off] = v;
}
#define ROUND_TOTAL (3L*SEG_DW + 3L*SEG_SW + SEG_X)

// ----------------- K1: router logits ---------------------------------------
__global__ __launch_bounds__(256) void logits_kernel(
    const float* __restrict__ x, const float* __restrict__ gw)
{
    int widx = blockIdx.x * 8 + (threadIdx.x >> 5);
    if (widx >= TT * NE) return;
    int t = widx / NE, e = widx - t * NE;
    int lane = threadIdx.x & 31;
    const float4* xr = (const float4*)(x + (size_t)t * HD);
    const float4* wr = (const float4*)(gw + (size_t)e * HD);
    float s = 0.f;
#pragma unroll
    for (int i = 0; i < HD / 128; i++) {
        float4 a = xr[lane + i * 32];
        float4 b = wr[lane + i * 32];
        s += a.x * b.x + a.y * b.y + a.z * b.z + a.w * b.w;
    }
#pragma unroll
    for (int o = 16; o; o >>= 1) s += __shfl_xor_sync(0xffffffffu, s, o);
    if (!lane) d_logits[widx] = s;
}

// ----------------- K2: per-token routing ------------------------------------
__global__ void routing_kernel()
{
    int t = blockIdx.x * blockDim.x + threadIdx.x;
    if (t >= TT) return;

    float s[EDN];
#pragma unroll
    for (int e = 0; e < EDN; e++) s[e] = d_logits[t * NE + e];

    float m = s[0];
#pragma unroll
    for (int e = 1; e < EDN; e++) m = fmaxf(m, s[e]);
    float p[EDN]; float den = 0.f;
#pragma unroll
    for (int e = 0; e < EDN; e++) { p[e] = expf(s[e] - m); den += p[e]; }
#pragma unroll
    for (int e = 0; e < EDN; e++) p[e] /= den;
    float sp[EDN];
#pragma unroll
    for (int e = 0; e < EDN; e++) sp[e] = p[e];
    for (int i = 1; i < EDN; i++) {
        float v = sp[i]; int j = i - 1;
        while (j >= 0 && sp[j] < v) { sp[j + 1] = sp[j]; j--; }
        sp[j + 1] = v;
    }
    float c = 0.f; int cnt = 0;
#pragma unroll
    for (int e = 0; e < EDN; e++) { c += sp[e]; if (c < TOPP) cnt++; }
    int dyn_k = min(cnt + 1, TOPK);

    float masked[EDN];
#pragma unroll
    for (int e = 0; e < EDN; e++) masked[e] = s[e];
    float mult[TOPK]; int sel[TOPK];
    for (int k = 0; k < TOPK; k++) {
        float thr = masked[0]; int sl = 0;
        for (int e = 1; e < EDN; e++)
            if (masked[e] > thr) { thr = masked[e]; sl = e; }
        bool keep[EDN];
        float gm = -INFINITY;
        for (int e = 0; e < EDN; e++) {
            float fac = fmaxf(fabsf(s[e]), fabsf(thr));
            float jm = (thr - s[e]) / fac;
            keep[e] = !(jm > JEPS2);
            if (keep[e]) gm = fmaxf(gm, masked[e]);
        }
        float d2 = 0.f;
        for (int e = 0; e < EDN; e++)
            if (keep[e]) d2 += expf(masked[e] - gm);
        mult[k] = expf(thr - gm) / d2;
        sel[k] = sl;
        masked[sl] = -INFINITY;
    }
    float rsum = 0.f;
#pragma unroll
    for (int k = 0; k < TOPK; k++) {
        if (k >= dyn_k) mult[k] = 0.f;
        rsum += mult[k];
    }
    int mk[EDN];
#pragma unroll
    for (int e = 0; e < EDN; e++) mk[e] = 0;
#pragma unroll
    for (int k = 0; k < TOPK; k++) {
        float r = mult[k] / rsum;
        d_rw[t * TOPK + k] = r;
        d_sel[t * TOPK + k] = sel[k];
        if (mult[k] > 0.f) mk[sel[k]] = 1;
    }
#pragma unroll
    for (int e = 0; e < EDN; e++) d_mask[t * EDN + e] = mk[e];
}

// ----------------- K3: capacity scan (warp-ballot, 1 CTA, 8 warps) ----------
__global__ __launch_bounds__(256) void scan_kernel()
{
    int w = threadIdx.x >> 5;
    int lane = threadIdx.x & 31;
    if (threadIdx.x < EDN) d_counts[threadIdx.x] = 0;
    int carry = 0;
    for (int c0 = 0; c0 < TT / 256; c0++) {
        int v[8];
#pragma unroll
        for (int j = 0; j < 8; j++) {
            int t = c0 * 256 + j * 32 + lane;
            v[j] = d_mask[t * EDN + w];
        }
#pragma unroll
        for (int j = 0; j < 8; j++) {
            unsigned bal = __ballot_sync(0xffffffffu, v[j]);
            int pre = __popc(bal & ((1u << lane) - 1));
            int incl = carry + pre + v[j];
            int t = c0 * 256 + j * 32 + lane;
            d_kept[t * EDN + w] = (v[j] && incl <= CAPV) ? 1 : 0;
            carry += __popc(bal);
        }
    }
}

// ----------------- K4: masked softmax + compaction --------------------------
__global__ void finalize_kernel()
{
    int t = blockIdx.x * blockDim.x + threadIdx.x;
    if (t >= TT) return;
    float l[NE];
#pragma unroll
    for (int i = 0; i < NE; i++) l[i] = d_logits[t * NE + i];
    int km[EDN];
#pragma unroll
    for (int e = 0; e < EDN; e++) km[e] = d_kept[t * EDN + e];

    float m = l[EDN];
#pragma unroll
    for (int e = 0; e < EDN; e++) if (km[e]) m = fmaxf(m, l[e]);
    float den = 0.f, dynsum = 0.f;
#pragma unroll
    for (int e = 0; e < EDN; e++)
        if (km[e]) { float ex = expf(l[e] - m); den += ex; dynsum += ex; }
    float exsh = expf(l[EDN] - m);
    den += exsh;
    d_wsh[t] = exsh / den;
    float sumdyn = dynsum / den;

#pragma unroll
    for (int k = 0; k < TOPK; k++) {
        float r = d_rw[t * TOPK + k];
        int e = d_sel[t * TOPK + k];
        int pos = -1;
        if (r > 0.f && km[e]) {
            pos = atomicAdd(&d_counts[e], 1);
            d_etok[e * CAPV + pos] = t;
            d_toke[t * TOPK + k] = e;
            d_tokw[t * TOPK + k] = r * sumdyn;
        }
        d_tokpos[t * TOPK + k] = pos;
    }
}

// ----------------- K5: gather x rows per expert (tf32-rounded) --------------
__global__ __launch_bounds__(256) void gather_kernel(const float* __restrict__ x)
{
    int b = blockIdx.x;
    int e = b / CAPV, i = b - e * CAPV;
    int c = threadIdx.x;
    float4* dst = (float4*)(d_xe + ((size_t)e * CAPV + i) * HD);
    if (i < d_counts[e]) {
        int t = d_etok[e * CAPV + i];
        float4 v = ((const float4*)(x + (size_t)t * HD))[c];
        v.x = rna_tf32(v.x); v.y = rna_tf32(v.y);
        v.z = rna_tf32(v.z); v.w = rna_tf32(v.w);
        dst[c] = v;
    } else {
        dst[c] = make_float4(0.f, 0.f, 0.f, 0.f);
    }
}

// ----------------- mma.sync tf32 GEMM: C[M,N] = A[M,K] @ B[N,K]^T -----------
// 128x256x32 CTA tile, 8 warps (2x4), warp tile 64x64, m16n8k8 tf32 MMA,
// 4-stage cp.async pipeline. Inputs pre-rounded to tf32.
// z < zSplit -> (Ba,Ca) else (Bb,Cb). mode=1: scale C row by rs[row].
__global__ __launch_bounds__(256, 1) void tf32_gemm_kernel(
    const float* __restrict__ A,
    const float* __restrict__ Ba, const float* __restrict__ Bb,
    float* __restrict__ Ca, float* __restrict__ Cb,
    int K, int N, size_t strA, size_t strB, size_t strC,
    int zSplit, int mode, const float* __restrict__ rs)
{
    extern __shared__ float smem[];
    int tid = threadIdx.x;
    int w = tid >> 5, lane = tid & 31;
    int wm = w >> 2, wn = w & 3;          // 2 x 4 warp grid, warp = 64x64
    int grp = lane >> 2, tig = lane & 3;

    int z = blockIdx.z;
    const float* Bp; float* Cp; int e;
    if (z < zSplit) { e = z; Bp = Ba; Cp = Ca; }
    else            { e = z - zSplit; Bp = Bb; Cp = Cb; }
    const float* Ap = A + (size_t)e * strA + (size_t)blockIdx.y * BM * K;
    Bp += (size_t)e * strB + (size_t)blockIdx.x * BN * K;
    Cp += (size_t)e * strC;

    float acc[4][8][4] = {};
    int KT = K / BK;

    // prologue
#pragma unroll
    for (int pt = 0; pt < NSTG - 1; pt++) {
        float* dstA = smem + pt * STAGE_FLOATS;
        float* dstB = dstA + BM * BKP;
#pragma unroll
        for (int i = 0; i < 4; i++) {
            int idx = tid + i * 256, row = idx >> 3, c = idx & 7;
            cp_async16(smem_u32(dstA + row * BKP + c * 4),
                       Ap + (size_t)row * K + pt * BK + c * 4);
        }
#pragma unroll
        for (int i = 0; i < 8; i++) {
            int idx = tid + i * 256, row = idx >> 3, c = idx & 7;
            cp_async16(smem_u32(dstB + row * BKP + c * 4),
                       Bp + (size_t)row * K + pt * BK + c * 4);
        }
        asm volatile("cp.async.commit_group;" ::: "memory");
    }

    for (int kt = 0; kt < KT; kt++) {
        cp_wait<NSTG - 2>();
        __syncthreads();
        const float* As = smem + (kt % NSTG) * STAGE_FLOATS;
        const float* Bs = As + BM * BKP;

#pragma unroll
        for (int k8 = 0; k8 < BK / 8; k8++) {
            int k0 = k8 * 8;
            uint32_t af[4][4], bf[8][2];
#pragma unroll
            for (int mf = 0; mf < 4; mf++) {
                const float* p = As + (wm * 64 + mf * 16 + grp) * BKP + k0 + tig;
                af[mf][0] = __float_as_uint(p[0]);
                af[mf][1] = __float_as_uint(p[8 * BKP]);
                af[mf][2] = __float_as_uint(p[4]);
                af[mf][3] = __float_as_uint(p[8 * BKP + 4]);
            }
#pragma unroll
            for (int nf = 0; nf < 8; nf++) {
                const float* p = Bs + (wn * 64 + nf * 8 + grp) * BKP + k0 + tig;
                bf[nf][0] = __float_as_uint(p[0]);
                bf[nf][1] = __float_as_uint(p[4]);
            }
#pragma unroll
            for (int mf = 0; mf < 4; mf++)
#pragma unroll
                for (int nf = 0; nf < 8; nf++)
                    asm volatile(
                        "mma.sync.aligned.m16n8k8.row.col.f32.tf32.tf32.f32 "
                        "{%0,%1,%2,%3}, {%4,%5,%6,%7}, {%8,%9}, {%0,%1,%2,%3};"
                        : "+f"(acc[mf][nf][0]), "+f"(acc[mf][nf][1]),
                          "+f"(acc[mf][nf][2]), "+f"(acc[mf][nf][3])
                        : "r"(af[mf][0]), "r"(af[mf][1]),
                          "r"(af[mf][2]), "r"(af[mf][3]),
                          "r"(bf[nf][0]), "r"(bf[nf][1]));
        }
        __syncthreads();

        int lt = kt + NSTG - 1;
        if (lt < KT) {
            float* dstA = smem + (lt % NSTG) * STAGE_FLOATS;
            float* dstB = dstA + BM * BKP;
#pragma unroll
            for (int i = 0; i < 4; i++) {
                int idx = tid + i * 256, row = idx >> 3, c = idx & 7;
                cp_async16(smem_u32(dstA + row * BKP + c * 4),
                           Ap + (size_t)row * K + lt * BK + c * 4);
            }
#pragma unroll
            for (int i = 0; i < 8; i++) {
                int idx = tid + i * 256, row = idx >> 3, c = idx & 7;
                cp_async16(smem_u32(dstB + row * BKP + c * 4),
                           Bp + (size_t)row * K + lt * BK + c * 4);
            }
            asm volatile("cp.async.commit_group;" ::: "memory");
        }
    }

    // epilogue
    int rowBase = blockIdx.y * BM, colBase = blockIdx.x * BN;
#pragma unroll
    for (int mf = 0; mf < 4; mf++) {
        int r0 = rowBase + wm * 64 + mf * 16 + grp;
        float s0 = mode ? rs[r0] : 1.f;
        float s1 = mode ? rs[r0 + 8] : 1.f;
#pragma unroll
        for (int nf = 0; nf < 8; nf++) {
            int col = colBase + wn * 64 + nf * 8 + tig * 2;
            float2 v0 = { acc[mf][nf][0] * s0, acc[mf][nf][1] * s0 };
            float2 v1 = { acc[mf][nf][2] * s1, acc[mf][nf][3] * s1 };
            *(float2*)(Cp + (size_t)r0 * N + col) = v0;
            *(float2*)(Cp + (size_t)(r0 + 8) * N + col) = v1;
        }
    }
}

// ----------------- silu(g)*u elementwise, rounded to tf32 -------------------
__global__ __launch_bounds__(256) void silu_mul_kernel(
    const float* __restrict__ g, const float* __restrict__ u,
    float* __restrict__ h, int n4)
{
    int i = blockIdx.x * blockDim.x + threadIdx.x;
    if (i >= n4) return;
    float4 gv = ((const float4*)g)[i];
    float4 uv = ((const float4*)u)[i];
    float4 r;
    r.x = rna_tf32(gv.x / (1.f + expf(-gv.x)) * uv.x);
    r.y = rna_tf32(gv.y / (1.f + expf(-gv.y)) * uv.y);
    r.z = rna_tf32(gv.z / (1.f + expf(-gv.z)) * uv.z);
    r.w = rna_tf32(gv.w / (1.f + expf(-gv.w)) * uv.w);
    ((float4*)h)[i] = r;
}

// ----------------- combine dyn expert outputs into out ----------------------
__global__ __launch_bounds__(256) void combine_kernel(float* __restrict__ out)
{
    int t = blockIdx.x;
    int c = threadIdx.x;
    float4 acc = ((float4*)(out + (size_t)t * HD))[c];
#pragma unroll
    for (int k = 0; k < TOPK; k++) {
        int pos = d_tokpos[t * TOPK + k];
        if (pos >= 0) {
            int e = d_toke[t * TOPK + k];
            float w = d_tokw[t * TOPK + k];
            float4 v = ((const float4*)(d_ybuf + ((size_t)e * CAPV + pos) * HD))[c];
            acc.x += w * v.x; acc.y += w * v.y;
            acc.z += w * v.z; acc.w += w * v.w;
        }
    }
    ((float4*)(out + (size_t)t * HD))[c] = acc;
}

// ----------------- host launcher --------------------------------------------
extern "C" void kernel_launch(void* const* d_in, const int* in_sizes, int n_in,
                              void* d_out, int out_size)
{
    const float* x   = (const float*)d_in[0];
    const float* gw  = (const float*)d_in[1];
    const float* dgw = (const float*)d_in[2];
    const float* duw = (const float*)d_in[3];
    const float* ddw = (const float*)d_in[4];
    const float* sgw = (const float*)d_in[5];
    const float* suw = (const float*)d_in[6];
    const float* sdw = (const float*)d_in[7];
    float* out = (float*)d_out;

    float *p_xe, *p_g, *p_u, *p_h, *p_y, *p_gs, *p_us, *p_hs, *p_wsh, *p_xr;
    float *p_dgw, *p_duw, *p_ddw, *p_sgw, *p_suw, *p_sdw;
    cudaGetSymbolAddress((void**)&p_xe, d_xe);
    cudaGetSymbolAddress((void**)&p_g, d_gbuf);
    cudaGetSymbolAddress((void**)&p_u, d_ubuf);
    cudaGetSymbolAddress((void**)&p_h, d_hbuf);
    cudaGetSymbolAddress((void**)&p_y, d_ybuf);
    cudaGetSymbolAddress((void**)&p_gs, d_gs);
    cudaGetSymbolAddress((void**)&p_us, d_us);
    cudaGetSymbolAddress((void**)&p_hs, d_hs);
    cudaGetSymbolAddress((void**)&p_wsh, d_wsh);
    cudaGetSymbolAddress((void**)&p_xr, d_xr);
    cudaGetSymbolAddress((void**)&p_dgw, d_dgw_r);
    cudaGetSymbolAddress((void**)&p_duw, d_duw_r);
    cudaGetSymbolAddress((void**)&p_ddw, d_ddw_r);
    cudaGetSymbolAddress((void**)&p_sgw, d_sgw_r);
    cudaGetSymbolAddress((void**)&p_suw, d_suw_r);
    cudaGetSymbolAddress((void**)&p_sdw, d_sdw_r);

    cudaFuncSetAttribute(tf32_gemm_kernel,
                         cudaFuncAttributeMaxDynamicSharedMemorySize, GEMM_SMEM);

    // single consolidated tf32 rounding prepass
    long nTot4 = ROUND_TOTAL;
    round_all_kernel<<<(int)((nTot4 + 255) / 256), 256>>>(
        (const float4*)dgw, (const float4*)duw, (const float4*)ddw,
        (const float4*)sgw, (const float4*)suw, (const float4*)sdw,
        (const float4*)x);

    // routing
    logits_kernel<<<(TT * NE + 7) / 8, 256>>>(x, gw);
    routing_kernel<<<(TT + 255) / 256, 256>>>();
    scan_kernel<<<1, 256>>>();
    finalize_kernel<<<(TT + 255) / 256, 256>>>();
    gather_kernel<<<EDN * CAPV, 256>>>(x);

    // shared expert gate+up (z=0: gate, z=1: up)
    dim3 gs1(IFX / BN, TT / BM, 2);
    tf32_gemm_kernel<<<gs1, 256, GEMM_SMEM>>>(
        p_xr, p_sgw, p_suw, p_gs, p_us, HD, IFX, 0, 0, 0, 1, 0, nullptr);

    // dyn experts gate+up (z<8: gate, z>=8: up)
    dim3 gd1(IDY / BN, CAPV / BM, 2 * EDN);
    tf32_gemm_kernel<<<gd1, 256, GEMM_SMEM>>>(
        p_xe, p_dgw, p_duw, p_g, p_u, HD, IDY,
        (size_t)CAPV * HD, (size_t)IDY * HD, (size_t)CAPV * IDY, EDN, 0, nullptr);
    int n4d = EDN * CAPV * IDY / 4;
    silu_mul_kernel<<<(n4d + 255) / 256, 256>>>(p_g, p_u, p_h, n4d);
    dim3 gd2(HD / BN, CAPV / BM, EDN);
    tf32_gemm_kernel<<<gd2, 256, GEMM_SMEM>>>(
        p_h, p_ddw, nullptr, p_y, nullptr, IDY, HD,
        (size_t)CAPV * IDY, (size_t)HD * IDY, (size_t)CAPV * HD, EDN, 0, nullptr);

    // shared expert silu + down (row-scaled by softmax weight, writes out)
    int n4s = TT * IFX / 4;
    silu_mul_kernel<<<(n4s + 255) / 256, 256>>>(p_gs, p_us, p_hs, n4s);
    dim3 gs2(HD / BN, TT / BM, 1);
    tf32_gemm_kernel<<<gs2, 256, GEMM_SMEM>>>(
        p_hs, p_sdw, nullptr, out, nullptr, IFX, HD, 0, 0, 0, 1, 1, p_wsh);

    // add dyn contributions
    combine_kernel<<<TT, 256>>>(out);
}

// round 7
// speedup vs baseline: 1.1738x; 1.1522x over previous
#include <cuda_runtime.h>
#include <math.h>
#include <float.h>
#include <stdint.h>

#define TT   4096
#define HD   1024
#define EDN  8
#define NE   9
#define IDY  512
#define IFX  2048
#define CAPV 640
#define TOPK 4
#define TOPP 0.75f
#define JEPS2 0.2f

// ---- mma.sync tf32 GEMM tiling: CTA 128x128x32, 8 warps (2x4), warp 64x32 --
#define BM   128
#define BN   128
#define BK   32
#define BKP  36                                // padded row (floats)
#define NSTG 3
#define STAGE_FLOATS ((BM + BN) * BKP)         // 9216
#define GEMM_SMEM (NSTG * STAGE_FLOATS * 4)    // 110592 B -> 2 CTAs/SM

__device__ __forceinline__ uint32_t smem_u32(const void* p) {
    uint32_t a;
    asm("{ .reg .u64 t; cvta.to.shared.u64 t, %1; cvt.u32.u64 %0, t; }" : "=r"(a) : "l"(p));
    return a;
}
__device__ __forceinline__ void cp_async16(uint32_t dst, const void* src) {
    asm volatile("cp.async.cg.shared.global [%0], [%1], 16;" :: "r"(dst), "l"(src));
}
template<int N> __device__ __forceinline__ void cp_wait() {
    asm volatile("cp.async.wait_group %0;" :: "n"(N) : "memory");
}
__device__ __forceinline__ float rna_tf32(float x) {
    uint32_t u;
    asm("cvt.rna.tf32.f32 %0, %1;" : "=r"(u) : "f"(x));
    return __uint_as_float(u);
}

// ----------------- device scratch (static, no allocations) -----------------
__device__ float d_logits[TT * NE];
__device__ int   d_sel[TT * TOPK];
__device__ float d_rw[TT * TOPK];
__device__ unsigned d_maskbits[TT];
__device__ int   d_kept[TT * EDN];
__device__ int   d_counts[EDN];
__device__ int   d_etok[EDN * CAPV];
__device__ int   d_tokpos[TT * TOPK];
__device__ int   d_toke[TT * TOPK];
__device__ float d_tokw[TT * TOPK];
__device__ float d_wsh[TT];
__device__ float d_xe[(size_t)EDN * CAPV * HD];
__device__ float d_gbuf[(size_t)EDN * CAPV * IDY];
__device__ float d_ubuf[(size_t)EDN * CAPV * IDY];
__device__ float d_hbuf[(size_t)EDN * CAPV * IDY];
__device__ float d_ybuf[(size_t)EDN * CAPV * HD];
__device__ float d_gs[(size_t)TT * IFX];
__device__ float d_us[(size_t)TT * IFX];
__device__ float d_hs[(size_t)TT * IFX];
// tf32-rounded copies
__device__ float d_xr[(size_t)TT * HD];
__device__ float d_dgw_r[(size_t)EDN * IDY * HD];
__device__ float d_duw_r[(size_t)EDN * IDY * HD];
__device__ float d_ddw_r[(size_t)EDN * HD * IDY];
__device__ float d_sgw_r[(size_t)IFX * HD];
__device__ float d_suw_r[(size_t)IFX * HD];
__device__ float d_sdw_r[(size_t)HD * IFX];

// ----------------- K0: segmented round-to-tf32 prepass ----------------------
#define SEG_DW (EDN * IDY * HD / 4)
#define SEG_SW (IFX * HD / 4)
#define SEG_X  (TT * HD / 4)
#define ROUND_TOTAL (3L*SEG_DW + 3L*SEG_SW + SEG_X)
__global__ __launch_bounds__(256) void round_all_kernel(
    const float4* __restrict__ dgw, const float4* __restrict__ duw,
    const float4* __restrict__ ddw, const float4* __restrict__ sgw,
    const float4* __restrict__ suw, const float4* __restrict__ sdw,
    const float4* __restrict__ x)
{
    long i = (long)blockIdx.x * blockDim.x + threadIdx.x;
    const float4* src; float4* dst; long off;
    if (i < SEG_DW)            { src = dgw; dst = (float4*)d_dgw_r; off = i; }
    else if (i < 2L*SEG_DW)    { src = duw; dst = (float4*)d_duw_r; off = i - SEG_DW; }
    else if (i < 3L*SEG_DW)    { src = ddw; dst = (float4*)d_ddw_r; off = i - 2L*SEG_DW; }
    else if (i < 3L*SEG_DW + SEG_SW)   { src = sgw; dst = (float4*)d_sgw_r; off = i - 3L*SEG_DW; }
    else if (i < 3L*SEG_DW + 2L*SEG_SW){ src = suw; dst = (float4*)d_suw_r; off = i - 3L*SEG_DW - SEG_SW; }
    else if (i < 3L*SEG_DW + 3L*SEG_SW){ src = sdw; dst = (float4*)d_sdw_r; off = i - 3L*SEG_DW - 2L*SEG_SW; }
    else if (i < ROUND_TOTAL)  { src = x;   dst = (float4*)d_xr;    off = i - 3L*SEG_DW - 3L*SEG_SW; }
    else return;
    float4 v = src[off];
    v.x = rna_tf32(v.x); v.y = rna_tf32(v.y);
    v.z = rna_tf32(v.z); v.w = rna_tf32(v.w);
    dst[off] = v;
}

// ----------------- K1: router logits ---------------------------------------
__global__ __launch_bounds__(256) void logits_kernel(
    const float* __restrict__ x, const float* __restrict__ gw)
{
    int widx = blockIdx.x * 8 + (threadIdx.x >> 5);
    if (widx >= TT * NE) return;
    int t = widx / NE, e = widx - t * NE;
    int lane = threadIdx.x & 31;
    const float4* xr = (const float4*)(x + (size_t)t * HD);
    const float4* wr = (const float4*)(gw + (size_t)e * HD);
    float s = 0.f;
#pragma unroll
    for (int i = 0; i < HD / 128; i++) {
        float4 a = xr[lane + i * 32];
        float4 b = wr[lane + i * 32];
        s += a.x * b.x + a.y * b.y + a.z * b.z + a.w * b.w;
    }
#pragma unroll
    for (int o = 16; o; o >>= 1) s += __shfl_xor_sync(0xffffffffu, s, o);
    if (!lane) d_logits[widx] = s;
}

// ----------------- K2: per-token routing (packs mask bits) ------------------
__global__ void routing_kernel()
{
    int t = blockIdx.x * blockDim.x + threadIdx.x;
    if (t >= TT) return;

    float s[EDN];
#pragma unroll
    for (int e = 0; e < EDN; e++) s[e] = d_logits[t * NE + e];

    float m = s[0];
#pragma unroll
    for (int e = 1; e < EDN; e++) m = fmaxf(m, s[e]);
    float p[EDN]; float den = 0.f;
#pragma unroll
    for (int e = 0; e < EDN; e++) { p[e] = expf(s[e] - m); den += p[e]; }
#pragma unroll
    for (int e = 0; e < EDN; e++) p[e] /= den;
    float sp[EDN];
#pragma unroll
    for (int e = 0; e < EDN; e++) sp[e] = p[e];
    for (int i = 1; i < EDN; i++) {
        float v = sp[i]; int j = i - 1;
        while (j >= 0 && sp[j] < v) { sp[j + 1] = sp[j]; j--; }
        sp[j + 1] = v;
    }
    float c = 0.f; int cnt = 0;
#pragma unroll
    for (int e = 0; e < EDN; e++) { c += sp[e]; if (c < TOPP) cnt++; }
    int dyn_k = min(cnt + 1, TOPK);

    float masked[EDN];
#pragma unroll
    for (int e = 0; e < EDN; e++) masked[e] = s[e];
    float mult[TOPK]; int sel[TOPK];
    for (int k = 0; k < TOPK; k++) {
        float thr = masked[0]; int sl = 0;
        for (int e = 1; e < EDN; e++)
            if (masked[e] > thr) { thr = masked[e]; sl = e; }
        bool keep[EDN];
        float gm = -INFINITY;
        for (int e = 0; e < EDN; e++) {
            float fac = fmaxf(fabsf(s[e]), fabsf(thr));
            float jm = (thr - s[e]) / fac;
            keep[e] = !(jm > JEPS2);
            if (keep[e]) gm = fmaxf(gm, masked[e]);
        }
        float d2 = 0.f;
        for (int e = 0; e < EDN; e++)
            if (keep[e]) d2 += expf(masked[e] - gm);
        mult[k] = expf(thr - gm) / d2;
        sel[k] = sl;
        masked[sl] = -INFINITY;
    }
    float rsum = 0.f;
#pragma unroll
    for (int k = 0; k < TOPK; k++) {
        if (k >= dyn_k) mult[k] = 0.f;
        rsum += mult[k];
    }
    unsigned mk = 0;
#pragma unroll
    for (int k = 0; k < TOPK; k++) {
        float r = mult[k] / rsum;
        d_rw[t * TOPK + k] = r;
        d_sel[t * TOPK + k] = sel[k];
        if (mult[k] > 0.f) mk |= (1u << sel[k]);
    }
    d_maskbits[t] = mk;
}

// ----------------- K3: capacity scan (packed bits, coalesced) ---------------
__global__ __launch_bounds__(256) void scan_kernel()
{
    int w = threadIdx.x >> 5;      // expert id
    int lane = threadIdx.x & 31;
    if (threadIdx.x < EDN) d_counts[threadIdx.x] = 0;
    int carry = 0;
    for (int c0 = 0; c0 < TT / 256; c0++) {
        unsigned v[8];
#pragma unroll
        for (int j = 0; j < 8; j++)
            v[j] = (d_maskbits[c0 * 256 + j * 32 + lane] >> w) & 1u;
#pragma unroll
        for (int j = 0; j < 8; j++) {
            unsigned bal = __ballot_sync(0xffffffffu, v[j]);
            int pre = __popc(bal & ((1u << lane) - 1));
            int incl = carry + pre + (int)v[j];
            int t = c0 * 256 + j * 32 + lane;
            d_kept[t * EDN + w] = (v[j] && incl <= CAPV) ? 1 : 0;
            carry += __popc(bal);
        }
    }
}

// ----------------- K4: masked softmax + compaction --------------------------
__global__ void finalize_kernel()
{
    int t = blockIdx.x * blockDim.x + threadIdx.x;
    if (t >= TT) return;
    float l[NE];
#pragma unroll
    for (int i = 0; i < NE; i++) l[i] = d_logits[t * NE + i];
    int km[EDN];
#pragma unroll
    for (int e = 0; e < EDN; e++) km[e] = d_kept[t * EDN + e];

    float m = l[EDN];
#pragma unroll
    for (int e = 0; e < EDN; e++) if (km[e]) m = fmaxf(m, l[e]);
    float den = 0.f, dynsum = 0.f;
#pragma unroll
    for (int e = 0; e < EDN; e++)
        if (km[e]) { float ex = expf(l[e] - m); den += ex; dynsum += ex; }
    float exsh = expf(l[EDN] - m);
    den += exsh;
    d_wsh[t] = exsh / den;
    float sumdyn = dynsum / den;

#pragma unroll
    for (int k = 0; k < TOPK; k++) {
        float r = d_rw[t * TOPK + k];
        int e = d_sel[t * TOPK + k];
        int pos = -1;
        if (r > 0.f && km[e]) {
            pos = atomicAdd(&d_counts[e], 1);
            d_etok[e * CAPV + pos] = t;
            d_toke[t * TOPK + k] = e;
            d_tokw[t * TOPK + k] = r * sumdyn;
        }
        d_tokpos[t * TOPK + k] = pos;
    }
}

// ----------------- K5: gather x rows per expert (tf32-rounded) --------------
__global__ __launch_bounds__(256) void gather_kernel(const float* __restrict__ x)
{
    int b = blockIdx.x;
    int e = b / CAPV, i = b - e * CAPV;
    int c = threadIdx.x;
    float4* dst = (float4*)(d_xe + ((size_t)e * CAPV + i) * HD);
    if (i < d_counts[e]) {
        int t = d_etok[e * CAPV + i];
        float4 v = ((const float4*)(x + (size_t)t * HD))[c];
        v.x = rna_tf32(v.x); v.y = rna_tf32(v.y);
        v.z = rna_tf32(v.z); v.w = rna_tf32(v.w);
        dst[c] = v;
    } else {
        dst[c] = make_float4(0.f, 0.f, 0.f, 0.f);
    }
}

// ----------------- mma.sync tf32 GEMM: C[M,N] = A[M,K] @ B[N,K]^T -----------
// 128x128x32 CTA tile, 8 warps (2x4), warp tile 64x32, m16n8k8 tf32 MMA,
// 3-stage cp.async pipeline, 2 CTAs/SM. Inputs pre-rounded to tf32.
// Tail waits are exact: tile kt must be complete before compute (the old
// unconditional wait<NSTG-2> left tile kt pending in the last iterations).
__global__ __launch_bounds__(256, 2) void tf32_gemm_kernel(
    const float* __restrict__ A,
    const float* __restrict__ Ba, const float* __restrict__ Bb,
    float* __restrict__ Ca, float* __restrict__ Cb,
    int K, int N, size_t strA, size_t strB, size_t strC,
    int zSplit, int mode, const float* __restrict__ rs)
{
    extern __shared__ float smem[];
    int tid = threadIdx.x;
    int w = tid >> 5, lane = tid & 31;
    int wm = w >> 2, wn = w & 3;          // 2 x 4 warp grid
    int grp = lane >> 2, tig = lane & 3;

    int z = blockIdx.z;
    const float* Bp; float* Cp; int e;
    if (z < zSplit) { e = z; Bp = Ba; Cp = Ca; }
    else            { e = z - zSplit; Bp = Bb; Cp = Cb; }
    const float* Ap = A + (size_t)e * strA + (size_t)blockIdx.y * BM * K;
    Bp += (size_t)e * strB + (size_t)blockIdx.x * BN * K;
    Cp += (size_t)e * strC;

    float acc[4][4][4] = {};
    int KT = K / BK;

    // prologue: stages 0..NSTG-2
#pragma unroll
    for (int pt = 0; pt < NSTG - 1; pt++) {
        float* dstA = smem + pt * STAGE_FLOATS;
        float* dstB = dstA + BM * BKP;
#pragma unroll
        for (int i = 0; i < 4; i++) {
            int idx = tid + i * 256, row = idx >> 3, c = idx & 7;
            cp_async16(smem_u32(dstA + row * BKP + c * 4),
                       Ap + (size_t)row * K + pt * BK + c * 4);
        }
#pragma unroll
        for (int i = 0; i < 4; i++) {
            int idx = tid + i * 256, row = idx >> 3, c = idx & 7;
            cp_async16(smem_u32(dstB + row * BKP + c * 4),
                       Bp + (size_t)row * K + pt * BK + c * 4);
        }
        asm volatile("cp.async.commit_group;" ::: "memory");
    }

    for (int kt = 0; kt < KT; kt++) {
        // exact wait: tile kt must be landed. allowed pending = KT-kt-1 in tail.
        if (kt < KT - 1) cp_wait<NSTG - 2>();   // NSTG-2 == 1
        else             cp_wait<0>();
        __syncthreads();
        const float* As = smem + (kt % NSTG) * STAGE_FLOATS;
        const float* Bs = As + BM * BKP;

#pragma unroll
        for (int k8 = 0; k8 < BK / 8; k8++) {
            int k0 = k8 * 8;
            uint32_t af[4][4], bf[4][2];
#pragma unroll
            for (int mf = 0; mf < 4; mf++) {
                const float* p = As + (wm * 64 + mf * 16 + grp) * BKP + k0 + tig;
                af[mf][0] = __float_as_uint(p[0]);
                af[mf][1] = __float_as_uint(p[8 * BKP]);
                af[mf][2] = __float_as_uint(p[4]);
                af[mf][3] = __float_as_uint(p[8 * BKP + 4]);
            }
#pragma unroll
            for (int nf = 0; nf < 4; nf++) {
                const float* p = Bs + (wn * 32 + nf * 8 + grp) * BKP + k0 + tig;
                bf[nf][0] = __float_as_uint(p[0]);
                bf[nf][1] = __float_as_uint(p[4]);
            }
#pragma unroll
            for (int mf = 0; mf < 4; mf++)
#pragma unroll
                for (int nf = 0; nf < 4; nf++)
                    asm volatile(
                        "mma.sync.aligned.m16n8k8.row.col.f32.tf32.tf32.f32 "
                        "{%0,%1,%2,%3}, {%4,%5,%6,%7}, {%8,%9}, {%0,%1,%2,%3};"
                        : "+f"(acc[mf][nf][0]), "+f"(acc[mf][nf][1]),
                          "+f"(acc[mf][nf][2]), "+f"(acc[mf][nf][3])
                        : "r"(af[mf][0]), "r"(af[mf][1]),
                          "r"(af[mf][2]), "r"(af[mf][3]),
                          "r"(bf[nf][0]), "r"(bf[nf][1]));
        }
        __syncthreads();

        int lt = kt + NSTG - 1;
        if (lt < KT) {
            float* dstA = smem + (lt % NSTG) * STAGE_FLOATS;
            float* dstB = dstA + BM * BKP;
#pragma unroll
            for (int i = 0; i < 4; i++) {
                int idx = tid + i * 256, row = idx >> 3, c = idx & 7;
                cp_async16(smem_u32(dstA + row * BKP + c * 4),
                           Ap + (size_t)row * K + lt * BK + c * 4);
            }
#pragma unroll
            for (int i = 0; i < 4; i++) {
                int idx = tid + i * 256, row = idx >> 3, c = idx & 7;
                cp_async16(smem_u32(dstB + row * BKP + c * 4),
                           Bp + (size_t)row * K + lt * BK + c * 4);
            }
            asm volatile("cp.async.commit_group;" ::: "memory");
        }
    }

    // epilogue
    int rowBase = blockIdx.y * BM, colBase = blockIdx.x * BN;
#pragma unroll
    for (int mf = 0; mf < 4; mf++) {
        int r0 = rowBase + wm * 64 + mf * 16 + grp;
        float s0 = mode ? rs[r0] : 1.f;
        float s1 = mode ? rs[r0 + 8] : 1.f;
#pragma unroll
        for (int nf = 0; nf < 4; nf++) {
            int col = colBase + wn * 32 + nf * 8 + tig * 2;
            float2 v0 = { acc[mf][nf][0] * s0, acc[mf][nf][1] * s0 };
            float2 v1 = { acc[mf][nf][2] * s1, acc[mf][nf][3] * s1 };
            *(float2*)(Cp + (size_t)r0 * N + col) = v0;
            *(float2*)(Cp + (size_t)(r0 + 8) * N + col) = v1;
        }
    }
}

// ----------------- silu(g)*u elementwise, rounded to tf32 -------------------
__global__ __launch_bounds__(256) void silu_mul_kernel(
    const float* __restrict__ g, const float* __restrict__ u,
    float* __restrict__ h, int n4)
{
    int i = blockIdx.x * blockDim.x + threadIdx.x;
    if (i >= n4) return;
    float4 gv = ((const float4*)g)[i];
    float4 uv = ((const float4*)u)[i];
    float4 r;
    r.x = rna_tf32(gv.x / (1.f + expf(-gv.x)) * uv.x);
    r.y = rna_tf32(gv.y / (1.f + expf(-gv.y)) * uv.y);
    r.z = rna_tf32(gv.z / (1.f + expf(-gv.z)) * uv.z);
    r.w = rna_tf32(gv.w / (1.f + expf(-gv.w)) * uv.w);
    ((float4*)h)[i] = r;
}

// ----------------- combine dyn expert outputs into out ----------------------
__global__ __launch_bounds__(256) void combine_kernel(float* __restrict__ out)
{
    int t = blockIdx.x;
    int c = threadIdx.x;
    float4 acc = ((float4*)(out + (size_t)t * HD))[c];
#pragma unroll
    for (int k = 0; k < TOPK; k++) {
        int pos = d_tokpos[t * TOPK + k];
        if (pos >= 0) {
            int e = d_toke[t * TOPK + k];
            float w = d_tokw[t * TOPK + k];
            float4 v = ((const float4*)(d_ybuf + ((size_t)e * CAPV + pos) * HD))[c];
            acc.x += w * v.x; acc.y += w * v.y;
            acc.z += w * v.z; acc.w += w * v.w;
        }
    }
    ((float4*)(out + (size_t)t * HD))[c] = acc;
}

// ----------------- host launcher --------------------------------------------
extern "C" void kernel_launch(void* const* d_in, const int* in_sizes, int n_in,
                              void* d_out, int out_size)
{
    const float* x   = (const float*)d_in[0];
    const float* gw  = (const float*)d_in[1];
    const float* dgw = (const float*)d_in[2];
    const float* duw = (const float*)d_in[3];
    const float* ddw = (const float*)d_in[4];
    const float* sgw = (const float*)d_in[5];
    const float* suw = (const float*)d_in[6];
    const float* sdw = (const float*)d_in[7];
    float* out = (float*)d_out;

    float *p_xe, *p_g, *p_u, *p_h, *p_y, *p_gs, *p_us, *p_hs, *p_wsh, *p_xr;
    float *p_dgw, *p_duw, *p_ddw, *p_sgw, *p_suw, *p_sdw;
    cudaGetSymbolAddress((void**)&p_xe, d_xe);
    cudaGetSymbolAddress((void**)&p_g, d_gbuf);
    cudaGetSymbolAddress((void**)&p_u, d_ubuf);
    cudaGetSymbolAddress((void**)&p_h, d_hbuf);
    cudaGetSymbolAddress((void**)&p_y, d_ybuf);
    cudaGetSymbolAddress((void**)&p_gs, d_gs);
    cudaGetSymbolAddress((void**)&p_us, d_us);
    cudaGetSymbolAddress((void**)&p_hs, d_hs);
    cudaGetSymbolAddress((void**)&p_wsh, d_wsh);
    cudaGetSymbolAddress((void**)&p_xr, d_xr);
    cudaGetSymbolAddress((void**)&p_dgw, d_dgw_r);
    cudaGetSymbolAddress((void**)&p_duw, d_duw_r);
    cudaGetSymbolAddress((void**)&p_ddw, d_ddw_r);
    cudaGetSymbolAddress((void**)&p_sgw, d_sgw_r);
    cudaGetSymbolAddress((void**)&p_suw, d_suw_r);
    cudaGetSymbolAddress((void**)&p_sdw, d_sdw_r);

    cudaFuncSetAttribute(tf32_gemm_kernel,
                         cudaFuncAttributeMaxDynamicSharedMemorySize, GEMM_SMEM);

    // single consolidated tf32 rounding prepass
    round_all_kernel<<<(int)((ROUND_TOTAL + 255) / 256), 256>>>(
        (const float4*)dgw, (const float4*)duw, (const float4*)ddw,
        (const float4*)sgw, (const float4*)suw, (const float4*)sdw,
        (const float4*)x);

    // routing
    logits_kernel<<<(TT * NE + 7) / 8, 256>>>(x, gw);
    routing_kernel<<<(TT + 255) / 256, 256>>>();
    scan_kernel<<<1, 256>>>();
    finalize_kernel<<<(TT + 255) / 256, 256>>>();
    gather_kernel<<<EDN * CAPV, 256>>>(x);

    // shared expert gate+up (z=0: gate, z=1: up)
    dim3 gs1(IFX / BN, TT / BM, 2);
    tf32_gemm_kernel<<<gs1, 256, GEMM_SMEM>>>(
        p_xr, p_sgw, p_suw, p_gs, p_us, HD, IFX, 0, 0, 0, 1, 0, nullptr);

    // dyn experts gate+up (z<8: gate, z>=8: up)
    dim3 gd1(IDY / BN, CAPV / BM, 2 * EDN);
    tf32_gemm_kernel<<<gd1, 256, GEMM_SMEM>>>(
        p_xe, p_dgw, p_duw, p_g, p_u, HD, IDY,
        (size_t)CAPV * HD, (size_t)IDY * HD, (size_t)CAPV * IDY, EDN, 0, nullptr);
    int n4d = EDN * CAPV * IDY / 4;
    silu_mul_kernel<<<(n4d + 255) / 256, 256>>>(p_g, p_u, p_h, n4d);
    dim3 gd2(HD / BN, CAPV / BM, EDN);
    tf32_gemm_kernel<<<gd2, 256, GEMM_SMEM>>>(
        p_h, p_ddw, nullptr, p_y, nullptr, IDY, HD,
        (size_t)CAPV * IDY, (size_t)HD * IDY, (size_t)CAPV * HD, EDN, 0, nullptr);

    // shared expert silu + down (row-scaled by softmax weight, writes out)
    int n4s = TT * IFX / 4;
    silu_mul_kernel<<<(n4s + 255) / 256, 256>>>(p_gs, p_us, p_hs, n4s);
    dim3 gs2(HD / BN, TT / BM, 1);
    tf32_gemm_kernel<<<gs2, 256, GEMM_SMEM>>>(
        p_hs, p_sdw, nullptr, out, nullptr, IFX, HD, 0, 0, 0, 1, 1, p_wsh);

    // add dyn contributions
    combine_kernel<<<TT, 256>>>(out);
}

// round 8
// speedup vs baseline: 1.2363x; 1.0532x over previous
#include <cuda_runtime.h>
#include <math.h>
#include <float.h>
#include <stdint.h>

#define TT   4096
#define HD   1024
#define EDN  8
#define NE   9
#define IDY  512
#define IFX  2048
#define CAPV 640
#define TOPK 4
#define TOPP 0.75f
#define JEPS2 0.2f

// ---- mma.sync tf32 GEMM tiling: CTA 128x128x32, 8 warps (2x4), warp 64x32 --
#define BM   128
#define BN   128
#define BK   32
#define BKP  36                                // padded row (floats)
#define NSTG 3
#define STAGE_FLOATS ((BM + BN) * BKP)         // 9216
#define GEMM_SMEM (NSTG * STAGE_FLOATS * 4)    // 110592 B -> 2 CTAs/SM

__device__ __forceinline__ uint32_t smem_u32(const void* p) {
    uint32_t a;
    asm("{ .reg .u64 t; cvta.to.shared.u64 t, %1; cvt.u32.u64 %0, t; }" : "=r"(a) : "l"(p));
    return a;
}
__device__ __forceinline__ void cp_async16(uint32_t dst, const void* src) {
    asm volatile("cp.async.cg.shared.global [%0], [%1], 16;" :: "r"(dst), "l"(src));
}
template<int N> __device__ __forceinline__ void cp_wait() {
    asm volatile("cp.async.wait_group %0;" :: "n"(N) : "memory");
}
__device__ __forceinline__ float rna_tf32(float x) {
    uint32_t u;
    asm("cvt.rna.tf32.f32 %0, %1;" : "=r"(u) : "f"(x));
    return __uint_as_float(u);
}
// ldmatrix x4 (b16 path; for tf32 each 8x4-tf32 tile == 8x8-b16 tile)
__device__ __forceinline__ void ldsm_x4(uint32_t& r0, uint32_t& r1,
                                        uint32_t& r2, uint32_t& r3, uint32_t addr) {
    asm volatile("ldmatrix.sync.aligned.m8n8.x4.shared.b16 {%0,%1,%2,%3}, [%4];"
                 : "=r"(r0), "=r"(r1), "=r"(r2), "=r"(r3) : "r"(addr));
}

// ----------------- device scratch (static, no allocations) -----------------
__device__ float d_logits[TT * NE];
__device__ int   d_sel[TT * TOPK];
__device__ float d_rw[TT * TOPK];
__device__ unsigned d_maskbits[TT];
__device__ int   d_kept[TT * EDN];
__device__ int   d_counts[EDN];
__device__ int   d_etok[EDN * CAPV];
__device__ int   d_tokpos[TT * TOPK];
__device__ int   d_toke[TT * TOPK];
__device__ float d_tokw[TT * TOPK];
__device__ float d_wsh[TT];
__device__ float d_xe[(size_t)EDN * CAPV * HD];
__device__ float d_gbuf[(size_t)EDN * CAPV * IDY];
__device__ float d_ubuf[(size_t)EDN * CAPV * IDY];
__device__ float d_hbuf[(size_t)EDN * CAPV * IDY];
__device__ float d_ybuf[(size_t)EDN * CAPV * HD];
__device__ float d_gs[(size_t)TT * IFX];
__device__ float d_us[(size_t)TT * IFX];
__device__ float d_hs[(size_t)TT * IFX];
// tf32-rounded copies
__device__ float d_xr[(size_t)TT * HD];
__device__ float d_dgw_r[(size_t)EDN * IDY * HD];
__device__ float d_duw_r[(size_t)EDN * IDY * HD];
__device__ float d_ddw_r[(size_t)EDN * HD * IDY];
__device__ float d_sgw_r[(size_t)IFX * HD];
__device__ float d_suw_r[(size_t)IFX * HD];
__device__ float d_sdw_r[(size_t)HD * IFX];

// ----------------- K0: segmented round-to-tf32 prepass ----------------------
#define SEG_DW (EDN * IDY * HD / 4)
#define SEG_SW (IFX * HD / 4)
#define SEG_X  (TT * HD / 4)
#define ROUND_TOTAL (3L*SEG_DW + 3L*SEG_SW + SEG_X)
__global__ __launch_bounds__(256) void round_all_kernel(
    const float4* __restrict__ dgw, const float4* __restrict__ duw,
    const float4* __restrict__ ddw, const float4* __restrict__ sgw,
    const float4* __restrict__ suw, const float4* __restrict__ sdw,
    const float4* __restrict__ x)
{
    long i = (long)blockIdx.x * blockDim.x + threadIdx.x;
    const float4* src; float4* dst; long off;
    if (i < SEG_DW)            { src = dgw; dst = (float4*)d_dgw_r; off = i; }
    else if (i < 2L*SEG_DW)    { src = duw; dst = (float4*)d_duw_r; off = i - SEG_DW; }
    else if (i < 3L*SEG_DW)    { src = ddw; dst = (float4*)d_ddw_r; off = i - 2L*SEG_DW; }
    else if (i < 3L*SEG_DW + SEG_SW)   { src = sgw; dst = (float4*)d_sgw_r; off = i - 3L*SEG_DW; }
    else if (i < 3L*SEG_DW + 2L*SEG_SW){ src = suw; dst = (float4*)d_suw_r; off = i - 3L*SEG_DW - SEG_SW; }
    else if (i < 3L*SEG_DW + 3L*SEG_SW){ src = sdw; dst = (float4*)d_sdw_r; off = i - 3L*SEG_DW - 2L*SEG_SW; }
    else if (i < ROUND_TOTAL)  { src = x;   dst = (float4*)d_xr;    off = i - 3L*SEG_DW - 3L*SEG_SW; }
    else return;
    float4 v = src[off];
    v.x = rna_tf32(v.x); v.y = rna_tf32(v.y);
    v.z = rna_tf32(v.z); v.w = rna_tf32(v.w);
    dst[off] = v;
}

// ----------------- K1: router logits ---------------------------------------
__global__ __launch_bounds__(256) void logits_kernel(
    const float* __restrict__ x, const float* __restrict__ gw)
{
    int widx = blockIdx.x * 8 + (threadIdx.x >> 5);
    if (widx >= TT * NE) return;
    int t = widx / NE, e = widx - t * NE;
    int lane = threadIdx.x & 31;
    const float4* xr = (const float4*)(x + (size_t)t * HD);
    const float4* wr = (const float4*)(gw + (size_t)e * HD);
    float s = 0.f;
#pragma unroll
    for (int i = 0; i < HD / 128; i++) {
        float4 a = xr[lane + i * 32];
        float4 b = wr[lane + i * 32];
        s += a.x * b.x + a.y * b.y + a.z * b.z + a.w * b.w;
    }
#pragma unroll
    for (int o = 16; o; o >>= 1) s += __shfl_xor_sync(0xffffffffu, s, o);
    if (!lane) d_logits[widx] = s;
}

// ----------------- K2: per-token routing (packs mask bits) ------------------
__global__ void routing_kernel()
{
    int t = blockIdx.x * blockDim.x + threadIdx.x;
    if (t >= TT) return;

    float s[EDN];
#pragma unroll
    for (int e = 0; e < EDN; e++) s[e] = d_logits[t * NE + e];

    float m = s[0];
#pragma unroll
    for (int e = 1; e < EDN; e++) m = fmaxf(m, s[e]);
    float p[EDN]; float den = 0.f;
#pragma unroll
    for (int e = 0; e < EDN; e++) { p[e] = expf(s[e] - m); den += p[e]; }
#pragma unroll
    for (int e = 0; e < EDN; e++) p[e] /= den;
    float sp[EDN];
#pragma unroll
    for (int e = 0; e < EDN; e++) sp[e] = p[e];
    for (int i = 1; i < EDN; i++) {
        float v = sp[i]; int j = i - 1;
        while (j >= 0 && sp[j] < v) { sp[j + 1] = sp[j]; j--; }
        sp[j + 1] = v;
    }
    float c = 0.f; int cnt = 0;
#pragma unroll
    for (int e = 0; e < EDN; e++) { c += sp[e]; if (c < TOPP) cnt++; }
    int dyn_k = min(cnt + 1, TOPK);

    float masked[EDN];
#pragma unroll
    for (int e = 0; e < EDN; e++) masked[e] = s[e];
    float mult[TOPK]; int sel[TOPK];
    for (int k = 0; k < TOPK; k++) {
        float thr = masked[0]; int sl = 0;
        for (int e = 1; e < EDN; e++)
            if (masked[e] > thr) { thr = masked[e]; sl = e; }
        bool keep[EDN];
        float gm = -INFINITY;
        for (int e = 0; e < EDN; e++) {
            float fac = fmaxf(fabsf(s[e]), fabsf(thr));
            float jm = (thr - s[e]) / fac;
            keep[e] = !(jm > JEPS2);
            if (keep[e]) gm = fmaxf(gm, masked[e]);
        }
        float d2 = 0.f;
        for (int e = 0; e < EDN; e++)
            if (keep[e]) d2 += expf(masked[e] - gm);
        mult[k] = expf(thr - gm) / d2;
        sel[k] = sl;
        masked[sl] = -INFINITY;
    }
    float rsum = 0.f;
#pragma unroll
    for (int k = 0; k < TOPK; k++) {
        if (k >= dyn_k) mult[k] = 0.f;
        rsum += mult[k];
    }
    unsigned mk = 0;
#pragma unroll
    for (int k = 0; k < TOPK; k++) {
        float r = mult[k] / rsum;
        d_rw[t * TOPK + k] = r;
        d_sel[t * TOPK + k] = sel[k];
        if (mult[k] > 0.f) mk |= (1u << sel[k]);
    }
    d_maskbits[t] = mk;
}

// ----------------- K3: capacity scan (8 CTAs, 1024 thr, block scan) ---------
__global__ __launch_bounds__(1024) void scan_kernel()
{
    int e = blockIdx.x;
    int lane = threadIdx.x & 31, w = threadIdx.x >> 5;
    __shared__ int woff[32];
    __shared__ int tot_s;
    if (threadIdx.x == 0) d_counts[e] = 0;
    int carry = 0;
    __syncthreads();
    for (int c0 = 0; c0 < TT / 1024; c0++) {
        int t = c0 * 1024 + threadIdx.x;
        int v = (int)((d_maskbits[t] >> e) & 1u);
        unsigned bal = __ballot_sync(0xffffffffu, v);
        int pre = __popc(bal & ((1u << lane) - 1));
        if (lane == 0) woff[w] = __popc(bal);
        __syncthreads();
        if (w == 0) {
            int val = woff[lane];
            int ex = val;
#pragma unroll
            for (int o = 1; o < 32; o <<= 1) {
                int n = __shfl_up_sync(0xffffffffu, ex, o);
                if (lane >= o) ex += n;
            }
            woff[lane] = ex - val;          // exclusive warp offset
            if (lane == 31) tot_s = ex;     // chunk total
        }
        __syncthreads();
        int incl = carry + woff[w] + pre + v;
        d_kept[t * EDN + e] = (v && incl <= CAPV) ? 1 : 0;
        carry += tot_s;
        __syncthreads();
    }
}

// ----------------- K4: masked softmax + compaction --------------------------
__global__ void finalize_kernel()
{
    int t = blockIdx.x * blockDim.x + threadIdx.x;
    if (t >= TT) return;
    float l[NE];
#pragma unroll
    for (int i = 0; i < NE; i++) l[i] = d_logits[t * NE + i];
    int km[EDN];
#pragma unroll
    for (int e = 0; e < EDN; e++) km[e] = d_kept[t * EDN + e];

    float m = l[EDN];
#pragma unroll
    for (int e = 0; e < EDN; e++) if (km[e]) m = fmaxf(m, l[e]);
    float den = 0.f, dynsum = 0.f;
#pragma unroll
    for (int e = 0; e < EDN; e++)
        if (km[e]) { float ex = expf(l[e] - m); den += ex; dynsum += ex; }
    float exsh = expf(l[EDN] - m);
    den += exsh;
    d_wsh[t] = exsh / den;
    float sumdyn = dynsum / den;

#pragma unroll
    for (int k = 0; k < TOPK; k++) {
        float r = d_rw[t * TOPK + k];
        int e = d_sel[t * TOPK + k];
        int pos = -1;
        if (r > 0.f && km[e]) {
            pos = atomicAdd(&d_counts[e], 1);
            d_etok[e * CAPV + pos] = t;
            d_toke[t * TOPK + k] = e;
            d_tokw[t * TOPK + k] = r * sumdyn;
        }
        d_tokpos[t * TOPK + k] = pos;
    }
}

// ----------------- K5: gather x rows per expert (tf32-rounded) --------------
__global__ __launch_bounds__(256) void gather_kernel(const float* __restrict__ x)
{
    int b = blockIdx.x;
    int e = b / CAPV, i = b - e * CAPV;
    int c = threadIdx.x;
    float4* dst = (float4*)(d_xe + ((size_t)e * CAPV + i) * HD);
    if (i < d_counts[e]) {
        int t = d_etok[e * CAPV + i];
        float4 v = ((const float4*)(x + (size_t)t * HD))[c];
        v.x = rna_tf32(v.x); v.y = rna_tf32(v.y);
        v.z = rna_tf32(v.z); v.w = rna_tf32(v.w);
        dst[c] = v;
    } else {
        dst[c] = make_float4(0.f, 0.f, 0.f, 0.f);
    }
}

// ----------------- mma.sync tf32 GEMM with ldmatrix fragment loads ----------
// 128x128x32 CTA tile, 8 warps (2x4), warp 64x32, m16n8k8 tf32 MMA,
// 3-stage cp.async pipeline, 2 CTAs/SM, exact tail waits.
// Fragments via ldmatrix.x4.b16 (8x4-tf32 tile == 8x8-b16 tile).
__global__ __launch_bounds__(256, 2) void tf32_gemm_kernel(
    const float* __restrict__ A,
    const float* __restrict__ Ba, const float* __restrict__ Bb,
    float* __restrict__ Ca, float* __restrict__ Cb,
    int K, int N, size_t strA, size_t strB, size_t strC,
    int zSplit, int mode, const float* __restrict__ rs)
{
    extern __shared__ float smem[];
    int tid = threadIdx.x;
    int w = tid >> 5, lane = tid & 31;
    int wm = w >> 2, wn = w & 3;          // 2 x 4 warp grid
    int grp = lane >> 2, tig = lane & 3;
    int q = lane >> 3, r8 = lane & 7;     // ldmatrix octet coords
    int aRow = (q & 1) * 8 + r8, aK = (q >> 1) * 4;   // A: tiles m0/m8 x k0/k4
    int bRow = (q >> 1) * 8 + r8, bK = (q & 1) * 4;   // B: tiles n0k0,n0k4,n8k0,n8k4

    int z = blockIdx.z;
    const float* Bp; float* Cp; int e;
    if (z < zSplit) { e = z; Bp = Ba; Cp = Ca; }
    else            { e = z - zSplit; Bp = Bb; Cp = Cb; }
    const float* Ap = A + (size_t)e * strA + (size_t)blockIdx.y * BM * K;
    Bp += (size_t)e * strB + (size_t)blockIdx.x * BN * K;
    Cp += (size_t)e * strC;

    float acc[4][4][4] = {};
    int KT = K / BK;

    // prologue: stages 0..NSTG-2
#pragma unroll
    for (int pt = 0; pt < NSTG - 1; pt++) {
        float* dstA = smem + pt * STAGE_FLOATS;
        float* dstB = dstA + BM * BKP;
#pragma unroll
        for (int i = 0; i < 4; i++) {
            int idx = tid + i * 256, row = idx >> 3, c = idx & 7;
            cp_async16(smem_u32(dstA + row * BKP + c * 4),
                       Ap + (size_t)row * K + pt * BK + c * 4);
        }
#pragma unroll
        for (int i = 0; i < 4; i++) {
            int idx = tid + i * 256, row = idx >> 3, c = idx & 7;
            cp_async16(smem_u32(dstB + row * BKP + c * 4),
                       Bp + (size_t)row * K + pt * BK + c * 4);
        }
        asm volatile("cp.async.commit_group;" ::: "memory");
    }

    for (int kt = 0; kt < KT; kt++) {
        if (kt < KT - 1) cp_wait<NSTG - 2>();
        else             cp_wait<0>();
        __syncthreads();
        const float* As = smem + (kt % NSTG) * STAGE_FLOATS;
        const float* Bs = As + BM * BKP;
        // per-lane base addresses for this stage
        uint32_t aBase = smem_u32(As + (wm * 64 + aRow) * BKP + aK);
        uint32_t bBase = smem_u32(Bs + (wn * 32 + bRow) * BKP + bK);

#pragma unroll
        for (int k8 = 0; k8 < BK / 8; k8++) {
            uint32_t kOfs = k8 * 8 * 4;
            uint32_t af[4][4], bf2[2][4];
#pragma unroll
            for (int mf = 0; mf < 4; mf++)
                ldsm_x4(af[mf][0], af[mf][1], af[mf][2], af[mf][3],
                        aBase + mf * (16 * BKP * 4) + kOfs);
#pragma unroll
            for (int pr = 0; pr < 2; pr++)
                ldsm_x4(bf2[pr][0], bf2[pr][1], bf2[pr][2], bf2[pr][3],
                        bBase + pr * (16 * BKP * 4) + kOfs);
#pragma unroll
            for (int mf = 0; mf < 4; mf++)
#pragma unroll
                for (int nf = 0; nf < 4; nf++) {
                    uint32_t b0 = bf2[nf >> 1][(nf & 1) * 2];
                    uint32_t b1 = bf2[nf >> 1][(nf & 1) * 2 + 1];
                    asm volatile(
                        "mma.sync.aligned.m16n8k8.row.col.f32.tf32.tf32.f32 "
                        "{%0,%1,%2,%3}, {%4,%5,%6,%7}, {%8,%9}, {%0,%1,%2,%3};"
                        : "+f"(acc[mf][nf][0]), "+f"(acc[mf][nf][1]),
                          "+f"(acc[mf][nf][2]), "+f"(acc[mf][nf][3])
                        : "r"(af[mf][0]), "r"(af[mf][1]),
                          "r"(af[mf][2]), "r"(af[mf][3]),
                          "r"(b0), "r"(b1));
                }
        }
        __syncthreads();

        int lt = kt + NSTG - 1;
        if (lt < KT) {
            float* dstA = smem + (lt % NSTG) * STAGE_FLOATS;
            float* dstB = dstA + BM * BKP;
#pragma unroll
            for (int i = 0; i < 4; i++) {
                int idx = tid + i * 256, row = idx >> 3, c = idx & 7;
                cp_async16(smem_u32(dstA + row * BKP + c * 4),
                           Ap + (size_t)row * K + lt * BK + c * 4);
            }
#pragma unroll
            for (int i = 0; i < 4; i++) {
                int idx = tid + i * 256, row = idx >> 3, c = idx & 7;
                cp_async16(smem_u32(dstB + row * BKP + c * 4),
                           Bp + (size_t)row * K + lt * BK + c * 4);
            }
            asm volatile("cp.async.commit_group;" ::: "memory");
        }
    }

    // epilogue
    int rowBase = blockIdx.y * BM, colBase = blockIdx.x * BN;
#pragma unroll
    for (int mf = 0; mf < 4; mf++) {
        int r0 = rowBase + wm * 64 + mf * 16 + grp;
        float s0 = mode ? rs[r0] : 1.f;
        float s1 = mode ? rs[r0 + 8] : 1.f;
#pragma unroll
        for (int nf = 0; nf < 4; nf++) {
            int col = colBase + wn * 32 + nf * 8 + tig * 2;
            float2 v0 = { acc[mf][nf][0] * s0, acc[mf][nf][1] * s0 };
            float2 v1 = { acc[mf][nf][2] * s1, acc[mf][nf][3] * s1 };
            *(float2*)(Cp + (size_t)r0 * N + col) = v0;
            *(float2*)(Cp + (size_t)(r0 + 8) * N + col) = v1;
        }
    }
}

// ----------------- silu(g)*u elementwise, rounded to tf32 -------------------
__global__ __launch_bounds__(256) void silu_mul_kernel(
    const float* __restrict__ g, const float* __restrict__ u,
    float* __restrict__ h, int n4)
{
    int i = blockIdx.x * blockDim.x + threadIdx.x;
    if (i >= n4) return;
    float4 gv = ((const float4*)g)[i];
    float4 uv = ((const float4*)u)[i];
    float4 r;
    r.x = rna_tf32(gv.x / (1.f + expf(-gv.x)) * uv.x);
    r.y = rna_tf32(gv.y / (1.f + expf(-gv.y)) * uv.y);
    r.z = rna_tf32(gv.z / (1.f + expf(-gv.z)) * uv.z);
    r.w = rna_tf32(gv.w / (1.f + expf(-gv.w)) * uv.w);
    ((float4*)h)[i] = r;
}

// ----------------- combine dyn expert outputs into out ----------------------
__global__ __launch_bounds__(256) void combine_kernel(float* __restrict__ out)
{
    int t = blockIdx.x;
    int c = threadIdx.x;
    float4 acc = ((float4*)(out + (size_t)t * HD))[c];
#pragma unroll
    for (int k = 0; k < TOPK; k++) {
        int pos = d_tokpos[t * TOPK + k];
        if (pos >= 0) {
            int e = d_toke[t * TOPK + k];
            float w = d_tokw[t * TOPK + k];
            float4 v = ((const float4*)(d_ybuf + ((size_t)e * CAPV + pos) * HD))[c];
            acc.x += w * v.x; acc.y += w * v.y;
            acc.z += w * v.z; acc.w += w * v.w;
        }
    }
    ((float4*)(out + (size_t)t * HD))[c] = acc;
}

// ----------------- host launcher --------------------------------------------
extern "C" void kernel_launch(void* const* d_in, const int* in_sizes, int n_in,
                              void* d_out, int out_size)
{
    const float* x   = (const float*)d_in[0];
    const float* gw  = (const float*)d_in[1];
    const float* dgw = (const float*)d_in[2];
    const float* duw = (const float*)d_in[3];
    const float* ddw = (const float*)d_in[4];
    const float* sgw = (const float*)d_in[5];
    const float* suw = (const float*)d_in[6];
    const float* sdw = (const float*)d_in[7];
    float* out = (float*)d_out;

    float *p_xe, *p_g, *p_u, *p_h, *p_y, *p_gs, *p_us, *p_hs, *p_wsh, *p_xr;
    float *p_dgw, *p_duw, *p_ddw, *p_sgw, *p_suw, *p_sdw;
    cudaGetSymbolAddress((void**)&p_xe, d_xe);
    cudaGetSymbolAddress((void**)&p_g, d_gbuf);
    cudaGetSymbolAddress((void**)&p_u, d_ubuf);
    cudaGetSymbolAddress((void**)&p_h, d_hbuf);
    cudaGetSymbolAddress((void**)&p_y, d_ybuf);
    cudaGetSymbolAddress((void**)&p_gs, d_gs);
    cudaGetSymbolAddress((void**)&p_us, d_us);
    cudaGetSymbolAddress((void**)&p_hs, d_hs);
    cudaGetSymbolAddress((void**)&p_wsh, d_wsh);
    cudaGetSymbolAddress((void**)&p_xr, d_xr);
    cudaGetSymbolAddress((void**)&p_dgw, d_dgw_r);
    cudaGetSymbolAddress((void**)&p_duw, d_duw_r);
    cudaGetSymbolAddress((void**)&p_ddw, d_ddw_r);
    cudaGetSymbolAddress((void**)&p_sgw, d_sgw_r);
    cudaGetSymbolAddress((void**)&p_suw, d_suw_r);
    cudaGetSymbolAddress((void**)&p_sdw, d_sdw_r);

    cudaFuncSetAttribute(tf32_gemm_kernel,
                         cudaFuncAttributeMaxDynamicSharedMemorySize, GEMM_SMEM);

    // single consolidated tf32 rounding prepass
    round_all_kernel<<<(int)((ROUND_TOTAL + 255) / 256), 256>>>(
        (const float4*)dgw, (const float4*)duw, (const float4*)ddw,
        (const float4*)sgw, (const float4*)suw, (const float4*)sdw,
        (const float4*)x);

    // routing
    logits_kernel<<<(TT * NE + 7) / 8, 256>>>(x, gw);
    routing_kernel<<<(TT + 255) / 256, 256>>>();
    scan_kernel<<<EDN, 1024>>>();
    finalize_kernel<<<(TT + 255) / 256, 256>>>();
    gather_kernel<<<EDN * CAPV, 256>>>(x);

    // shared expert gate+up (z=0: gate, z=1: up)
    dim3 gs1(IFX / BN, TT / BM, 2);
    tf32_gemm_kernel<<<gs1, 256, GEMM_SMEM>>>(
        p_xr, p_sgw, p_suw, p_gs, p_us, HD, IFX, 0, 0, 0, 1, 0, nullptr);

    // dyn experts gate+up (z<8: gate, z>=8: up)
    dim3 gd1(IDY / BN, CAPV / BM, 2 * EDN);
    tf32_gemm_kernel<<<gd1, 256, GEMM_SMEM>>>(
        p_xe, p_dgw, p_duw, p_g, p_u, HD, IDY,
        (size_t)CAPV * HD, (size_t)IDY * HD, (size_t)CAPV * IDY, EDN, 0, nullptr);
    int n4d = EDN * CAPV * IDY / 4;
    silu_mul_kernel<<<(n4d + 255) / 256, 256>>>(p_g, p_u, p_h, n4d);
    dim3 gd2(HD / BN, CAPV / BM, EDN);
    tf32_gemm_kernel<<<gd2, 256, GEMM_SMEM>>>(
        p_h, p_ddw, nullptr, p_y, nullptr, IDY, HD,
        (size_t)CAPV * IDY, (size_t)HD * IDY, (size_t)CAPV * HD, EDN, 0, nullptr);

    // shared expert silu + down (row-scaled by softmax weight, writes out)
    int n4s = TT * IFX / 4;
    silu_mul_kernel<<<(n4s + 255) / 256, 256>>>(p_gs, p_us, p_hs, n4s);
    dim3 gs2(HD / BN, TT / BM, 1);
    tf32_gemm_kernel<<<gs2, 256, GEMM_SMEM>>>(
        p_hs, p_sdw, nullptr, out, nullptr, IFX, HD, 0, 0, 0, 1, 1, p_wsh);

    // add dyn contributions
    combine_kernel<<<TT, 256>>>(out);
}

// round 13
// speedup vs baseline: 1.4220x; 1.1502x over previous
#include <cuda_runtime.h>
#include <math.h>
#include <float.h>
#include <stdint.h>

#define TT   4096
#define HD   1024
#define EDN  8
#define NE   9
#define IDY  512
#define IFX  2048
#define CAPV 640
#define TOPK 4
#define TOPP 0.75f
#define JEPS2 0.2f

// ---- mma.sync tf32 GEMM tiling: CTA 128x128x32, 8 warps (2x4), warp 64x32 --
#define BM   128
#define BN   128
#define BK   32
#define BKP  36
#define NSTG 3
#define STAGE_FLOATS ((BM + BN) * BKP)         // 9216
#define GEMM_SMEM (NSTG * STAGE_FLOATS * 4)    // 110592 B -> 2 CTAs/SM

__device__ __forceinline__ uint32_t smem_u32(const void* p) {
    uint32_t a;
    asm("{ .reg .u64 t; cvta.to.shared.u64 t, %1; cvt.u32.u64 %0, t; }" : "=r"(a) : "l"(p));
    return a;
}
__device__ __forceinline__ void cp_async16(uint32_t dst, const void* src) {
    asm volatile("cp.async.cg.shared.global [%0], [%1], 16;" :: "r"(dst), "l"(src));
}
template<int N> __device__ __forceinline__ void cp_wait() {
    asm volatile("cp.async.wait_group %0;" :: "n"(N) : "memory");
}
__device__ __forceinline__ float rna_tf32(float x) {
    uint32_t u;
    asm("cvt.rna.tf32.f32 %0, %1;" : "=r"(u) : "f"(x));
    return __uint_as_float(u);
}
__device__ __forceinline__ void ldsm_x4(uint32_t& r0, uint32_t& r1,
                                        uint32_t& r2, uint32_t& r3, uint32_t addr) {
    asm volatile("ldmatrix.sync.aligned.m8n8.x4.shared.b16 {%0,%1,%2,%3}, [%4];"
                 : "=r"(r0), "=r"(r1), "=r"(r2), "=r"(r3) : "r"(addr));
}

// ----------------- device scratch (static, no allocations) -----------------
__device__ float d_logits[TT * NE];
__device__ int   d_sel[TT * TOPK];
__device__ float d_rw[TT * TOPK];
__device__ unsigned d_maskbits[TT];
__device__ int   d_kept[TT * EDN];
__device__ int   d_counts[EDN];
__device__ int   d_etok[EDN * CAPV];
__device__ int   d_tokpos[TT * TOPK];
__device__ int   d_toke[TT * TOPK];
__device__ float d_tokw[TT * TOPK];
__device__ float d_wsh[TT];
__device__ float d_xe[(size_t)EDN * CAPV * HD];
__device__ float d_gbuf[(size_t)EDN * CAPV * IDY];
__device__ float d_ubuf[(size_t)EDN * CAPV * IDY];
__device__ float d_hbuf[(size_t)EDN * CAPV * IDY];
__device__ float d_ybuf[(size_t)EDN * CAPV * HD];
__device__ float d_gs[(size_t)TT * IFX];
__device__ float d_us[(size_t)TT * IFX];
__device__ float d_hs[(size_t)TT * IFX];
// tf32-rounded copies
__device__ float d_xr[(size_t)TT * HD];
__device__ float d_dgw_r[(size_t)EDN * IDY * HD];
__device__ float d_duw_r[(size_t)EDN * IDY * HD];
__device__ float d_ddw_r[(size_t)EDN * HD * IDY];
__device__ float d_sgw_r[(size_t)IFX * HD];
__device__ float d_suw_r[(size_t)IFX * HD];
__device__ float d_sdw_r[(size_t)HD * IFX];

// ----------------- K0: segmented round-to-tf32 prepass ----------------------
#define SEG_DW (EDN * IDY * HD / 4)
#define SEG_SW (IFX * HD / 4)
#define SEG_X  (TT * HD / 4)
#define ROUND_TOTAL (3L*SEG_DW + 3L*SEG_SW + SEG_X)
__global__ __launch_bounds__(256) void round_all_kernel(
    const float4* __restrict__ dgw, const float4* __restrict__ duw,
    const float4* __restrict__ ddw, const float4* __restrict__ sgw,
    const float4* __restrict__ suw, const float4* __restrict__ sdw,
    const float4* __restrict__ x)
{
    long i = (long)blockIdx.x * blockDim.x + threadIdx.x;
    const float4* src; float4* dst; long off;
    if (i < SEG_DW)            { src = dgw; dst = (float4*)d_dgw_r; off = i; }
    else if (i < 2L*SEG_DW)    { src = duw; dst = (float4*)d_duw_r; off = i - SEG_DW; }
    else if (i < 3L*SEG_DW)    { src = ddw; dst = (float4*)d_ddw_r; off = i - 2L*SEG_DW; }
    else if (i < 3L*SEG_DW + SEG_SW)   { src = sgw; dst = (float4*)d_sgw_r; off = i - 3L*SEG_DW; }
    else if (i < 3L*SEG_DW + 2L*SEG_SW){ src = suw; dst = (float4*)d_suw_r; off = i - 3L*SEG_DW - SEG_SW; }
    else if (i < 3L*SEG_DW + 3L*SEG_SW){ src = sdw; dst = (float4*)d_sdw_r; off = i - 3L*SEG_DW - 2L*SEG_SW; }
    else if (i < ROUND_TOTAL)  { src = x;   dst = (float4*)d_xr;    off = i - 3L*SEG_DW - 3L*SEG_SW; }
    else return;
    float4 v = src[off];
    v.x = rna_tf32(v.x); v.y = rna_tf32(v.y);
    v.z = rna_tf32(v.z); v.w = rna_tf32(v.w);
    dst[off] = v;
}

// ----------------- K1: router logits ---------------------------------------
__global__ __launch_bounds__(256) void logits_kernel(
    const float* __restrict__ x, const float* __restrict__ gw)
{
    int widx = blockIdx.x * 8 + (threadIdx.x >> 5);
    if (widx >= TT * NE) return;
    int t = widx / NE, e = widx - t * NE;
    int lane = threadIdx.x & 31;
    const float4* xr = (const float4*)(x + (size_t)t * HD);
    const float4* wr = (const float4*)(gw + (size_t)e * HD);
    float s = 0.f;
#pragma unroll
    for (int i = 0; i < HD / 128; i++) {
        float4 a = xr[lane + i * 32];
        float4 b = wr[lane + i * 32];
        s += a.x * b.x + a.y * b.y + a.z * b.z + a.w * b.w;
    }
#pragma unroll
    for (int o = 16; o; o >>= 1) s += __shfl_xor_sync(0xffffffffu, s, o);
    if (!lane) d_logits[widx] = s;
}

// ----------------- K2: per-token routing (packs mask bits) ------------------
__global__ void routing_kernel()
{
    int t = blockIdx.x * blockDim.x + threadIdx.x;
    if (t >= TT) return;

    float s[EDN];
#pragma unroll
    for (int e = 0; e < EDN; e++) s[e] = d_logits[t * NE + e];

    float m = s[0];
#pragma unroll
    for (int e = 1; e < EDN; e++) m = fmaxf(m, s[e]);
    float p[EDN]; float den = 0.f;
#pragma unroll
    for (int e = 0; e < EDN; e++) { p[e] = expf(s[e] - m); den += p[e]; }
#pragma unroll
    for (int e = 0; e < EDN; e++) p[e] /= den;
    float sp[EDN];
#pragma unroll
    for (int e = 0; e < EDN; e++) sp[e] = p[e];
    for (int i = 1; i < EDN; i++) {
        float v = sp[i]; int j = i - 1;
        while (j >= 0 && sp[j] < v) { sp[j + 1] = sp[j]; j--; }
        sp[j + 1] = v;
    }
    float c = 0.f; int cnt = 0;
#pragma unroll
    for (int e = 0; e < EDN; e++) { c += sp[e]; if (c < TOPP) cnt++; }
    int dyn_k = min(cnt + 1, TOPK);

    float masked[EDN];
#pragma unroll
    for (int e = 0; e < EDN; e++) masked[e] = s[e];
    float mult[TOPK]; int sel[TOPK];
    for (int k = 0; k < TOPK; k++) {
        float thr = masked[0]; int sl = 0;
        for (int e = 1; e < EDN; e++)
            if (masked[e] > thr) { thr = masked[e]; sl = e; }
        bool keep[EDN];
        float gm = -INFINITY;
        for (int e = 0; e < EDN; e++) {
            float fac = fmaxf(fabsf(s[e]), fabsf(thr));
            float jm = (thr - s[e]) / fac;
            keep[e] = !(jm > JEPS2);
            if (keep[e]) gm = fmaxf(gm, masked[e]);
        }
        float d2 = 0.f;
        for (int e = 0; e < EDN; e++)
            if (keep[e]) d2 += expf(masked[e] - gm);
        mult[k] = expf(thr - gm) / d2;
        sel[k] = sl;
        masked[sl] = -INFINITY;
    }
    float rsum = 0.f;
#pragma unroll
    for (int k = 0; k < TOPK; k++) {
        if (k >= dyn_k) mult[k] = 0.f;
        rsum += mult[k];
    }
    unsigned mk = 0;
#pragma unroll
    for (int k = 0; k < TOPK; k++) {
        float r = mult[k] / rsum;
        d_rw[t * TOPK + k] = r;
        d_sel[t * TOPK + k] = sel[k];
        if (mult[k] > 0.f) mk |= (1u << sel[k]);
    }
    d_maskbits[t] = mk;
}

// ----------------- K3: capacity scan (8 CTAs, 1024 thr, block scan) ---------
__global__ __launch_bounds__(1024) void scan_kernel()
{
    int e = blockIdx.x;
    int lane = threadIdx.x & 31, w = threadIdx.x >> 5;
    __shared__ int woff[32];
    __shared__ int tot_s;
    if (threadIdx.x == 0) d_counts[e] = 0;
    int carry = 0;
    __syncthreads();
    for (int c0 = 0; c0 < TT / 1024; c0++) {
        int t = c0 * 1024 + threadIdx.x;
        int v = (int)((d_maskbits[t] >> e) & 1u);
        unsigned bal = __ballot_sync(0xffffffffu, v);
        int pre = __popc(bal & ((1u << lane) - 1));
        if (lane == 0) woff[w] = __popc(bal);
        __syncthreads();
        if (w == 0) {
            int val = woff[lane];
            int ex = val;
#pragma unroll
            for (int o = 1; o < 32; o <<= 1) {
                int n = __shfl_up_sync(0xffffffffu, ex, o);
                if (lane >= o) ex += n;
            }
            woff[lane] = ex - val;
            if (lane == 31) tot_s = ex;
        }
        __syncthreads();
        int incl = carry + woff[w] + pre + v;
        d_kept[t * EDN + e] = (v && incl <= CAPV) ? 1 : 0;
        carry += tot_s;
        __syncthreads();
    }
}

// ----------------- K4: masked softmax + compaction --------------------------
__global__ void finalize_kernel()
{
    int t = blockIdx.x * blockDim.x + threadIdx.x;
    if (t >= TT) return;
    float l[NE];
#pragma unroll
    for (int i = 0; i < NE; i++) l[i] = d_logits[t * NE + i];
    int km[EDN];
#pragma unroll
    for (int e = 0; e < EDN; e++) km[e] = d_kept[t * EDN + e];

    float m = l[EDN];
#pragma unroll
    for (int e = 0; e < EDN; e++) if (km[e]) m = fmaxf(m, l[e]);
    float den = 0.f, dynsum = 0.f;
#pragma unroll
    for (int e = 0; e < EDN; e++)
        if (km[e]) { float ex = expf(l[e] - m); den += ex; dynsum += ex; }
    float exsh = expf(l[EDN] - m);
    den += exsh;
    d_wsh[t] = exsh / den;
    float sumdyn = dynsum / den;

#pragma unroll
    for (int k = 0; k < TOPK; k++) {
        float r = d_rw[t * TOPK + k];
        int e = d_sel[t * TOPK + k];
        int pos = -1;
        if (r > 0.f && km[e]) {
            pos = atomicAdd(&d_counts[e], 1);
            d_etok[e * CAPV + pos] = t;
            d_toke[t * TOPK + k] = e;
            d_tokw[t * TOPK + k] = r * sumdyn;
        }
        d_tokpos[t * TOPK + k] = pos;
    }
}

// ----------------- K5: gather x rows per expert (tf32-rounded) --------------
__global__ __launch_bounds__(256) void gather_kernel(const float* __restrict__ x)
{
    int b = blockIdx.x;
    int e = b / CAPV, i = b - e * CAPV;
    int c = threadIdx.x;
    float4* dst = (float4*)(d_xe + ((size_t)e * CAPV + i) * HD);
    if (i < d_counts[e]) {
        int t = d_etok[e * CAPV + i];
        float4 v = ((const float4*)(x + (size_t)t * HD))[c];
        v.x = rna_tf32(v.x); v.y = rna_tf32(v.y);
        v.z = rna_tf32(v.z); v.w = rna_tf32(v.w);
        dst[c] = v;
    } else {
        dst[c] = make_float4(0.f, 0.f, 0.f, 0.f);
    }
}

// ----------------- shared GEMM body: C[128,128] tile = A@B^T ----------------
// ldmatrix fragments, single __syncthreads per K-tile, exact tail waits.
__device__ __forceinline__ void gemm_body(
    const float* __restrict__ Ap, const float* __restrict__ Bp,
    float* __restrict__ Cp, int K, int N, int rowBase, int colBase,
    int mode, const float* __restrict__ rs, float* smem)
{
    int tid = threadIdx.x;
    int w = tid >> 5, lane = tid & 31;
    int wm = w >> 2, wn = w & 3;
    int grp = lane >> 2, tig = lane & 3;
    int q = lane >> 3, r8 = lane & 7;
    int aRow = (q & 1) * 8 + r8, aK = (q >> 1) * 4;
    int bRow = (q >> 1) * 8 + r8, bK = (q & 1) * 4;

    const float* Ag = Ap + (size_t)rowBase * K;
    const float* Bg = Bp + (size_t)colBase * K;

    float acc[4][4][4] = {};
    int KT = K / BK;

    // prologue: stages 0..NSTG-2
#pragma unroll
    for (int pt = 0; pt < NSTG - 1; pt++) {
        float* dstA = smem + pt * STAGE_FLOATS;
        float* dstB = dstA + BM * BKP;
#pragma unroll
        for (int i = 0; i < 4; i++) {
            int idx = tid + i * 256, row = idx >> 3, c = idx & 7;
            cp_async16(smem_u32(dstA + row * BKP + c * 4),
                       Ag + (size_t)row * K + pt * BK + c * 4);
        }
#pragma unroll
        for (int i = 0; i < 4; i++) {
            int idx = tid + i * 256, row = idx >> 3, c = idx & 7;
            cp_async16(smem_u32(dstB + row * BKP + c * 4),
                       Bg + (size_t)row * K + pt * BK + c * 4);
        }
        asm volatile("cp.async.commit_group;" ::: "memory");
    }

    for (int kt = 0; kt < KT; kt++) {
        if (kt < KT - 1) cp_wait<1>();
        else             cp_wait<0>();
        __syncthreads();

        // issue next tile's loads first (stage (kt-1)%NSTG — its readers
        // finished compute of iter kt-1 before this barrier)
        int lt = kt + NSTG - 1;
        if (lt < KT) {
            float* dstA = smem + (lt % NSTG) * STAGE_FLOATS;
            float* dstB = dstA + BM * BKP;
#pragma unroll
            for (int i = 0; i < 4; i++) {
                int idx = tid + i * 256, row = idx >> 3, c = idx & 7;
                cp_async16(smem_u32(dstA + row * BKP + c * 4),
                           Ag + (size_t)row * K + lt * BK + c * 4);
            }
#pragma unroll
            for (int i = 0; i < 4; i++) {
                int idx = tid + i * 256, row = idx >> 3, c = idx & 7;
                cp_async16(smem_u32(dstB + row * BKP + c * 4),
                           Bg + (size_t)row * K + lt * BK + c * 4);
            }
            asm volatile("cp.async.commit_group;" ::: "memory");
        }

        const float* As = smem + (kt % NSTG) * STAGE_FLOATS;
        const float* Bs = As + BM * BKP;
        uint32_t aBase = smem_u32(As + (wm * 64 + aRow) * BKP + aK);
        uint32_t bBase = smem_u32(Bs + (wn * 32 + bRow) * BKP + bK);

#pragma unroll
        for (int k8 = 0; k8 < BK / 8; k8++) {
            uint32_t kOfs = k8 * 8 * 4;
            uint32_t af[4][4], bf2[2][4];
#pragma unroll
            for (int mf = 0; mf < 4; mf++)
                ldsm_x4(af[mf][0], af[mf][1], af[mf][2], af[mf][3],
                        aBase + mf * (16 * BKP * 4) + kOfs);
#pragma unroll
            for (int pr = 0; pr < 2; pr++)
                ldsm_x4(bf2[pr][0], bf2[pr][1], bf2[pr][2], bf2[pr][3],
                        bBase + pr * (16 * BKP * 4) + kOfs);
#pragma unroll
            for (int mf = 0; mf < 4; mf++)
#pragma unroll
                for (int nf = 0; nf < 4; nf++) {
                    uint32_t b0 = bf2[nf >> 1][(nf & 1) * 2];
                    uint32_t b1 = bf2[nf >> 1][(nf & 1) * 2 + 1];
                    asm volatile(
                        "mma.sync.aligned.m16n8k8.row.col.f32.tf32.tf32.f32 "
                        "{%0,%1,%2,%3}, {%4,%5,%6,%7}, {%8,%9}, {%0,%1,%2,%3};"
                        : "+f"(acc[mf][nf][0]), "+f"(acc[mf][nf][1]),
                          "+f"(acc[mf][nf][2]), "+f"(acc[mf][nf][3])
                        : "r"(af[mf][0]), "r"(af[mf][1]),
                          "r"(af[mf][2]), "r"(af[mf][3]),
                          "r"(b0), "r"(b1));
                }
        }
    }

    // epilogue
#pragma unroll
    for (int mf = 0; mf < 4; mf++) {
        int r0 = rowBase + wm * 64 + mf * 16 + grp;
        float s0 = mode ? rs[r0] : 1.f;
        float s1 = mode ? rs[r0 + 8] : 1.f;
#pragma unroll
        for (int nf = 0; nf < 4; nf++) {
            int col = colBase + wn * 32 + nf * 8 + tig * 2;
            float2 v0 = { acc[mf][nf][0] * s0, acc[mf][nf][1] * s0 };
            float2 v1 = { acc[mf][nf][2] * s1, acc[mf][nf][3] * s1 };
            *(float2*)(Cp + (size_t)r0 * N + col) = v0;
            *(float2*)(Cp + (size_t)(r0 + 8) * N + col) = v1;
        }
    }
}

// ----------------- merged gate+up GEMM (shared + dyn, K=1024) ---------------
// flat grid: [0,1024) shared gate/up tiles (512 each), [1024,1344) dyn
// (2 gate/up x 8 experts x 20 tiles = 320).
__global__ __launch_bounds__(256, 2) void gemm_gateup_kernel(
    const float* __restrict__ xr, const float* __restrict__ sgw,
    const float* __restrict__ suw, float* __restrict__ gs, float* __restrict__ us,
    const float* __restrict__ xe, const float* __restrict__ dgw,
    const float* __restrict__ duw, float* __restrict__ g, float* __restrict__ u)
{
    extern __shared__ float smem[];
    int b = blockIdx.x;
    const float *Ap, *Bp; float* Cp; int N, ty, tx;
    if (b < 1024) {                      // shared expert: 2 x (32 y-tiles x 16 x-tiles)
        N = IFX;
        int gu = b >> 9, t = b & 511;
        ty = t >> 4; tx = t & 15;
        Ap = xr;
        Bp = gu ? suw : sgw;
        Cp = gu ? us : gs;
    } else {                             // dyn experts: 2 x 8 x (5 y-tiles x 4 x-tiles)
        N = IDY;
        int idx = b - 1024;              // [0,320)
        int gu = idx >= 160;
        int r = idx - gu * 160;          // [0,160)
        int e = r / 20, t = r - e * 20;
        ty = t >> 2; tx = t & 3;
        Ap = xe + (size_t)e * CAPV * HD;
        Bp = (gu ? duw : dgw) + (size_t)e * IDY * HD;
        Cp = (gu ? u : g) + (size_t)e * CAPV * IDY;
    }
    gemm_body(Ap, Bp, Cp, HD, N, ty * BM, tx * BN, 0, nullptr, smem);
}

// ----------------- merged down GEMM (shared K=2048 + dyn K=512) -------------
// flat grid: [0,256) shared down (32 y x 8 x, rowscale),
//            [256,576) dyn down (8 experts x (5 y x 8 x) = 320).
__global__ __launch_bounds__(256, 2) void gemm_down_kernel(
    const float* __restrict__ hs, const float* __restrict__ sdw,
    float* __restrict__ outp, const float* __restrict__ wsh,
    const float* __restrict__ h, const float* __restrict__ ddw,
    float* __restrict__ y)
{
    extern __shared__ float smem[];
    int b = blockIdx.x;
    const float *Ap, *Bp; float* Cp; const float* rs; int K, mode, ty, tx;
    if (b < 256) {
        K = IFX; mode = 1; rs = wsh;
        ty = b >> 3; tx = b & 7;
        Ap = hs; Bp = sdw; Cp = outp;
    } else {
        K = IDY; mode = 0; rs = nullptr;
        int idx = b - 256;               // [0,320)
        int e = idx / 40, t = idx - e * 40;
        ty = t >> 3; tx = t & 7;
        Ap = h + (size_t)e * CAPV * IDY;
        Bp = ddw + (size_t)e * HD * IDY;
        Cp = y + (size_t)e * CAPV * HD;
    }
    gemm_body(Ap, Bp, Cp, K, HD, ty * BM, tx * BN, mode, rs, smem);
}

// ----------------- merged silu(g)*u (dyn + shared), rounded to tf32 ---------
#define N4D (EDN * CAPV * IDY / 4)
#define N4S (TT * IFX / 4)
__global__ __launch_bounds__(256) void silu_all_kernel()
{
    int i = blockIdx.x * blockDim.x + threadIdx.x;
    const float4 *gp, *up; float4* hp; int off;
    if (i < N4D)            { gp = (const float4*)d_gbuf; up = (const float4*)d_ubuf;
                              hp = (float4*)d_hbuf; off = i; }
    else if (i < N4D + N4S) { gp = (const float4*)d_gs; up = (const float4*)d_us;
                              hp = (float4*)d_hs; off = i - N4D; }
    else return;
    float4 gv = gp[off];
    float4 uv = up[off];
    float4 r;
    r.x = rna_tf32(gv.x / (1.f + expf(-gv.x)) * uv.x);
    r.y = rna_tf32(gv.y / (1.f + expf(-gv.y)) * uv.y);
    r.z = rna_tf32(gv.z / (1.f + expf(-gv.z)) * uv.z);
    r.w = rna_tf32(gv.w / (1.f + expf(-gv.w)) * uv.w);
    hp[off] = r;
}

// ----------------- combine dyn expert outputs into out ----------------------
__global__ __launch_bounds__(256) void combine_kernel(float* __restrict__ out)
{
    int t = blockIdx.x;
    int c = threadIdx.x;
    float4 acc = ((float4*)(out + (size_t)t * HD))[c];
#pragma unroll
    for (int k = 0; k < TOPK; k++) {
        int pos = d_tokpos[t * TOPK + k];
        if (pos >= 0) {
            int e = d_toke[t * TOPK + k];
            float w = d_tokw[t * TOPK + k];
            float4 v = ((const float4*)(d_ybuf + ((size_t)e * CAPV + pos) * HD))[c];
            acc.x += w * v.x; acc.y += w * v.y;
            acc.z += w * v.z; acc.w += w * v.w;
        }
    }
    ((float4*)(out + (size_t)t * HD))[c] = acc;
}

// ----------------- host launcher --------------------------------------------
extern "C" void kernel_launch(void* const* d_in, const int* in_sizes, int n_in,
                              void* d_out, int out_size)
{
    const float* x   = (const float*)d_in[0];
    const float* gw  = (const float*)d_in[1];
    const float* dgw = (const float*)d_in[2];
    const float* duw = (const float*)d_in[3];
    const float* ddw = (const float*)d_in[4];
    const float* sgw = (const float*)d_in[5];
    const float* suw = (const float*)d_in[6];
    const float* sdw = (const float*)d_in[7];
    float* out = (float*)d_out;

    float *p_xe, *p_g, *p_u, *p_h, *p_y, *p_gs, *p_us, *p_hs, *p_wsh, *p_xr;
    float *p_dgw, *p_duw, *p_ddw, *p_sgw, *p_suw, *p_sdw;
    cudaGetSymbolAddress((void**)&p_xe, d_xe);
    cudaGetSymbolAddress((void**)&p_g, d_gbuf);
    cudaGetSymbolAddress((void**)&p_u, d_ubuf);
    cudaGetSymbolAddress((void**)&p_h, d_hbuf);
    cudaGetSymbolAddress((void**)&p_y, d_ybuf);
    cudaGetSymbolAddress((void**)&p_gs, d_gs);
    cudaGetSymbolAddress((void**)&p_us, d_us);
    cudaGetSymbolAddress((void**)&p_hs, d_hs);
    cudaGetSymbolAddress((void**)&p_wsh, d_wsh);
    cudaGetSymbolAddress((void**)&p_xr, d_xr);
    cudaGetSymbolAddress((void**)&p_dgw, d_dgw_r);
    cudaGetSymbolAddress((void**)&p_duw, d_duw_r);
    cudaGetSymbolAddress((void**)&p_ddw, d_ddw_r);
    cudaGetSymbolAddress((void**)&p_sgw, d_sgw_r);
    cudaGetSymbolAddress((void**)&p_suw, d_suw_r);
    cudaGetSymbolAddress((void**)&p_sdw, d_sdw_r);

    cudaFuncSetAttribute(gemm_gateup_kernel,
                         cudaFuncAttributeMaxDynamicSharedMemorySize, GEMM_SMEM);
    cudaFuncSetAttribute(gemm_down_kernel,
                         cudaFuncAttributeMaxDynamicSharedMemorySize, GEMM_SMEM);

    // tf32 rounding prepass (one launch)
    round_all_kernel<<<(int)((ROUND_TOTAL + 255) / 256), 256>>>(
        (const float4*)dgw, (const float4*)duw, (const float4*)ddw,
        (const float4*)sgw, (const float4*)suw, (const float4*)sdw,
        (const float4*)x);

    // routing
    logits_kernel<<<(TT * NE + 7) / 8, 256>>>(x, gw);
    routing_kernel<<<(TT + 255) / 256, 256>>>();
    scan_kernel<<<EDN, 1024>>>();
    finalize_kernel<<<(TT + 255) / 256, 256>>>();
    gather_kernel<<<EDN * CAPV, 256>>>(x);

    // merged gate+up GEMM (shared + dyn), merged silu, merged down GEMM
    gemm_gateup_kernel<<<1344, 256, GEMM_SMEM>>>(
        p_xr, p_sgw, p_suw, p_gs, p_us, p_xe, p_dgw, p_duw, p_g, p_u);
    silu_all_kernel<<<(N4D + N4S + 255) / 256, 256>>>();
    gemm_down_kernel<<<576, 256, GEMM_SMEM>>>(
        p_hs, p_sdw, out, p_wsh, p_h, p_ddw, p_y);

    // add dyn contributions
    combine_kernel<<<TT, 256>>>(out);
}

// round 14
// speedup vs baseline: 1.4740x; 1.0366x over previous
#include <cuda_runtime.h>
#include <math.h>
#include <float.h>
#include <stdint.h>

#define TT   4096
#define HD   1024
#define EDN  8
#define NE   9
#define IDY  512
#define IFX  2048
#define CAPV 640
#define TOPK 4
#define TOPP 0.75f
#define JEPS2 0.2f

// ---- mma.sync tf32 GEMM tiling: CTA 128x128x32, 8 warps (2x4), warp 64x32 --
#define BM   128
#define BN   128
#define BK   32
#define BKP  36
#define NSTG 3
#define STAGE_FLOATS ((BM + BN) * BKP)         // 9216
#define GEMM_SMEM (NSTG * STAGE_FLOATS * 4)    // 110592 B -> 2 CTAs/SM

__device__ __forceinline__ uint32_t smem_u32(const void* p) {
    uint32_t a;
    asm("{ .reg .u64 t; cvta.to.shared.u64 t, %1; cvt.u32.u64 %0, t; }" : "=r"(a) : "l"(p));
    return a;
}
__device__ __forceinline__ void cp_async16(uint32_t dst, const void* src) {
    asm volatile("cp.async.cg.shared.global [%0], [%1], 16;" :: "r"(dst), "l"(src));
}
template<int N> __device__ __forceinline__ void cp_wait() {
    asm volatile("cp.async.wait_group %0;" :: "n"(N) : "memory");
}
__device__ __forceinline__ float rna_tf32(float x) {
    uint32_t u;
    asm("cvt.rna.tf32.f32 %0, %1;" : "=r"(u) : "f"(x));
    return __uint_as_float(u);
}
__device__ __forceinline__ void ldsm_x4(uint32_t& r0, uint32_t& r1,
                                        uint32_t& r2, uint32_t& r3, uint32_t addr) {
    asm volatile("ldmatrix.sync.aligned.m8n8.x4.shared.b16 {%0,%1,%2,%3}, [%4];"
                 : "=r"(r0), "=r"(r1), "=r"(r2), "=r"(r3) : "r"(addr));
}
__device__ __forceinline__ float silu_mul_rna(float g, float u) {
    return rna_tf32(g / (1.f + expf(-g)) * u);
}

// ----------------- device scratch (static, no allocations) -----------------
__device__ float d_logits[TT * NE];
__device__ int   d_sel[TT * TOPK];
__device__ float d_rw[TT * TOPK];
__device__ unsigned d_maskbits[TT];
__device__ int   d_kept[TT * EDN];
__device__ int   d_counts[EDN];
__device__ int   d_etok[EDN * CAPV];
__device__ int   d_tokpos[TT * TOPK];
__device__ int   d_toke[TT * TOPK];
__device__ float d_tokw[TT * TOPK];
__device__ float d_wsh[TT];
__device__ float d_xe[(size_t)EDN * CAPV * HD];
__device__ float d_hbuf[(size_t)EDN * CAPV * IDY];
__device__ float d_ybuf[(size_t)EDN * CAPV * HD];
__device__ float d_hs[(size_t)TT * IFX];
// tf32-rounded copies
__device__ float d_xr[(size_t)TT * HD];
__device__ float d_dgw_r[(size_t)EDN * IDY * HD];
__device__ float d_duw_r[(size_t)EDN * IDY * HD];
__device__ float d_ddw_r[(size_t)EDN * HD * IDY];
__device__ float d_sgw_r[(size_t)IFX * HD];
__device__ float d_suw_r[(size_t)IFX * HD];
__device__ float d_sdw_r[(size_t)HD * IFX];

// ----------------- K0: segmented round-to-tf32 prepass ----------------------
#define SEG_DW (EDN * IDY * HD / 4)
#define SEG_SW (IFX * HD / 4)
#define SEG_X  (TT * HD / 4)
#define ROUND_TOTAL (3L*SEG_DW + 3L*SEG_SW + SEG_X)
__global__ __launch_bounds__(256) void round_all_kernel(
    const float4* __restrict__ dgw, const float4* __restrict__ duw,
    const float4* __restrict__ ddw, const float4* __restrict__ sgw,
    const float4* __restrict__ suw, const float4* __restrict__ sdw,
    const float4* __restrict__ x)
{
    long i = (long)blockIdx.x * blockDim.x + threadIdx.x;
    const float4* src; float4* dst; long off;
    if (i < SEG_DW)            { src = dgw; dst = (float4*)d_dgw_r; off = i; }
    else if (i < 2L*SEG_DW)    { src = duw; dst = (float4*)d_duw_r; off = i - SEG_DW; }
    else if (i < 3L*SEG_DW)    { src = ddw; dst = (float4*)d_ddw_r; off = i - 2L*SEG_DW; }
    else if (i < 3L*SEG_DW + SEG_SW)   { src = sgw; dst = (float4*)d_sgw_r; off = i - 3L*SEG_DW; }
    else if (i < 3L*SEG_DW + 2L*SEG_SW){ src = suw; dst = (float4*)d_suw_r; off = i - 3L*SEG_DW - SEG_SW; }
    else if (i < 3L*SEG_DW + 3L*SEG_SW){ src = sdw; dst = (float4*)d_sdw_r; off = i - 3L*SEG_DW - 2L*SEG_SW; }
    else if (i < ROUND_TOTAL)  { src = x;   dst = (float4*)d_xr;    off = i - 3L*SEG_DW - 3L*SEG_SW; }
    else return;
    float4 v = src[off];
    v.x = rna_tf32(v.x); v.y = rna_tf32(v.y);
    v.z = rna_tf32(v.z); v.w = rna_tf32(v.w);
    dst[off] = v;
}

// ----------------- K1: router logits ---------------------------------------
__global__ __launch_bounds__(256) void logits_kernel(
    const float* __restrict__ x, const float* __restrict__ gw)
{
    int widx = blockIdx.x * 8 + (threadIdx.x >> 5);
    if (widx >= TT * NE) return;
    int t = widx / NE, e = widx - t * NE;
    int lane = threadIdx.x & 31;
    const float4* xr = (const float4*)(x + (size_t)t * HD);
    const float4* wr = (const float4*)(gw + (size_t)e * HD);
    float s = 0.f;
#pragma unroll
    for (int i = 0; i < HD / 128; i++) {
        float4 a = xr[lane + i * 32];
        float4 b = wr[lane + i * 32];
        s += a.x * b.x + a.y * b.y + a.z * b.z + a.w * b.w;
    }
#pragma unroll
    for (int o = 16; o; o >>= 1) s += __shfl_xor_sync(0xffffffffu, s, o);
    if (!lane) d_logits[widx] = s;
}

// ----------------- K2: per-token routing (packs mask bits) ------------------
__global__ void routing_kernel()
{
    int t = blockIdx.x * blockDim.x + threadIdx.x;
    if (t >= TT) return;

    float s[EDN];
#pragma unroll
    for (int e = 0; e < EDN; e++) s[e] = d_logits[t * NE + e];

    float m = s[0];
#pragma unroll
    for (int e = 1; e < EDN; e++) m = fmaxf(m, s[e]);
    float p[EDN]; float den = 0.f;
#pragma unroll
    for (int e = 0; e < EDN; e++) { p[e] = expf(s[e] - m); den += p[e]; }
#pragma unroll
    for (int e = 0; e < EDN; e++) p[e] /= den;
    float sp[EDN];
#pragma unroll
    for (int e = 0; e < EDN; e++) sp[e] = p[e];
    for (int i = 1; i < EDN; i++) {
        float v = sp[i]; int j = i - 1;
        while (j >= 0 && sp[j] < v) { sp[j + 1] = sp[j]; j--; }
        sp[j + 1] = v;
    }
    float c = 0.f; int cnt = 0;
#pragma unroll
    for (int e = 0; e < EDN; e++) { c += sp[e]; if (c < TOPP) cnt++; }
    int dyn_k = min(cnt + 1, TOPK);

    float masked[EDN];
#pragma unroll
    for (int e = 0; e < EDN; e++) masked[e] = s[e];
    float mult[TOPK]; int sel[TOPK];
    for (int k = 0; k < TOPK; k++) {
        float thr = masked[0]; int sl = 0;
        for (int e = 1; e < EDN; e++)
            if (masked[e] > thr) { thr = masked[e]; sl = e; }
        bool keep[EDN];
        float gm = -INFINITY;
        for (int e = 0; e < EDN; e++) {
            float fac = fmaxf(fabsf(s[e]), fabsf(thr));
            float jm = (thr - s[e]) / fac;
            keep[e] = !(jm > JEPS2);
            if (keep[e]) gm = fmaxf(gm, masked[e]);
        }
        float d2 = 0.f;
        for (int e = 0; e < EDN; e++)
            if (keep[e]) d2 += expf(masked[e] - gm);
        mult[k] = expf(thr - gm) / d2;
        sel[k] = sl;
        masked[sl] = -INFINITY;
    }
    float rsum = 0.f;
#pragma unroll
    for (int k = 0; k < TOPK; k++) {
        if (k >= dyn_k) mult[k] = 0.f;
        rsum += mult[k];
    }
    unsigned mk = 0;
#pragma unroll
    for (int k = 0; k < TOPK; k++) {
        float r = mult[k] / rsum;
        d_rw[t * TOPK + k] = r;
        d_sel[t * TOPK + k] = sel[k];
        if (mult[k] > 0.f) mk |= (1u << sel[k]);
    }
    d_maskbits[t] = mk;
}

// ----------------- K3: capacity scan (8 CTAs, 1024 thr, block scan) ---------
__global__ __launch_bounds__(1024) void scan_kernel()
{
    int e = blockIdx.x;
    int lane = threadIdx.x & 31, w = threadIdx.x >> 5;
    __shared__ int woff[32];
    __shared__ int tot_s;
    if (threadIdx.x == 0) d_counts[e] = 0;
    int carry = 0;
    __syncthreads();
    for (int c0 = 0; c0 < TT / 1024; c0++) {
        int t = c0 * 1024 + threadIdx.x;
        int v = (int)((d_maskbits[t] >> e) & 1u);
        unsigned bal = __ballot_sync(0xffffffffu, v);
        int pre = __popc(bal & ((1u << lane) - 1));
        if (lane == 0) woff[w] = __popc(bal);
        __syncthreads();
        if (w == 0) {
            int val = woff[lane];
            int ex = val;
#pragma unroll
            for (int o = 1; o < 32; o <<= 1) {
                int n = __shfl_up_sync(0xffffffffu, ex, o);
                if (lane >= o) ex += n;
            }
            woff[lane] = ex - val;
            if (lane == 31) tot_s = ex;
        }
        __syncthreads();
        int incl = carry + woff[w] + pre + v;
        d_kept[t * EDN + e] = (v && incl <= CAPV) ? 1 : 0;
        carry += tot_s;
        __syncthreads();
    }
}

// ----------------- K4: masked softmax + compaction --------------------------
__global__ void finalize_kernel()
{
    int t = blockIdx.x * blockDim.x + threadIdx.x;
    if (t >= TT) return;
    float l[NE];
#pragma unroll
    for (int i = 0; i < NE; i++) l[i] = d_logits[t * NE + i];
    int km[EDN];
#pragma unroll
    for (int e = 0; e < EDN; e++) km[e] = d_kept[t * EDN + e];

    float m = l[EDN];
#pragma unroll
    for (int e = 0; e < EDN; e++) if (km[e]) m = fmaxf(m, l[e]);
    float den = 0.f, dynsum = 0.f;
#pragma unroll
    for (int e = 0; e < EDN; e++)
        if (km[e]) { float ex = expf(l[e] - m); den += ex; dynsum += ex; }
    float exsh = expf(l[EDN] - m);
    den += exsh;
    d_wsh[t] = exsh / den;
    float sumdyn = dynsum / den;

#pragma unroll
    for (int k = 0; k < TOPK; k++) {
        float r = d_rw[t * TOPK + k];
        int e = d_sel[t * TOPK + k];
        int pos = -1;
        if (r > 0.f && km[e]) {
            pos = atomicAdd(&d_counts[e], 1);
            d_etok[e * CAPV + pos] = t;
            d_toke[t * TOPK + k] = e;
            d_tokw[t * TOPK + k] = r * sumdyn;
        }
        d_tokpos[t * TOPK + k] = pos;
    }
}

// ----------------- K5: gather x rows per expert (tf32-rounded) --------------
__global__ __launch_bounds__(256) void gather_kernel(const float* __restrict__ x)
{
    int b = blockIdx.x;
    int e = b / CAPV, i = b - e * CAPV;
    int c = threadIdx.x;
    float4* dst = (float4*)(d_xe + ((size_t)e * CAPV + i) * HD);
    if (i < d_counts[e]) {
        int t = d_etok[e * CAPV + i];
        float4 v = ((const float4*)(x + (size_t)t * HD))[c];
        v.x = rna_tf32(v.x); v.y = rna_tf32(v.y);
        v.z = rna_tf32(v.z); v.w = rna_tf32(v.w);
        dst[c] = v;
    } else {
        dst[c] = make_float4(0.f, 0.f, 0.f, 0.f);
    }
}

// ===================== fused gate+up GEMM + silu ============================
// CTA computes a 128(M) x 64(cols) h tile: B smem rows interleave gate/up at
// 8-row granularity (rows 16t..16t+7 = gate col-group t, 16t+8..+15 = up).
// Fragment nf even = gate, nf odd = up for SAME output cols -> thread-local
// silu. K = HD = 1024 always.
__global__ __launch_bounds__(256, 2) void gemm_gateup_fused(
    const float* __restrict__ xr, const float* __restrict__ sgw,
    const float* __restrict__ suw, float* __restrict__ hsO,
    const float* __restrict__ xe, const float* __restrict__ dgw,
    const float* __restrict__ duw, float* __restrict__ hO)
{
    extern __shared__ float smem[];
    int b = blockIdx.x;
    const float *Ap, *Bg_, *Bu_; float* Hp; int N, ty, tx;
    if (b < 1024) {                      // shared expert: 32 y x 32 x(64-col)
        N = IFX;
        ty = b >> 5; tx = b & 31;
        Ap = xr; Bg_ = sgw; Bu_ = suw; Hp = hsO;
    } else {                             // dyn: 8 experts x (5 y x 8 x)
        N = IDY;
        int idx = b - 1024;              // [0,320)
        int e = idx / 40, t = idx - e * 40;
        ty = t >> 3; tx = t & 7;
        Ap = xe + (size_t)e * CAPV * HD;
        Bg_ = dgw + (size_t)e * IDY * HD;
        Bu_ = duw + (size_t)e * IDY * HD;
        Hp = hO + (size_t)e * CAPV * IDY;
    }
    int rowBase = ty * BM, colBase = tx * 64;
    const int K = HD;

    int tid = threadIdx.x;
    int w = tid >> 5, lane = tid & 31;
    int wm = w >> 2, wn = w & 3;
    int grp = lane >> 2, tig = lane & 3;
    int q = lane >> 3, r8 = lane & 7;
    int aRow = (q & 1) * 8 + r8, aK = (q >> 1) * 4;
    int bRow = (q >> 1) * 8 + r8, bK = (q & 1) * 4;

    // per-thread loader source rows (4 chunks each for A and B)
    const float* aSrc[4];
    const float* bSrc[4];
    int sRow[4];
#pragma unroll
    for (int i = 0; i < 4; i++) {
        int idx = tid + i * 256, row = idx >> 3;
        sRow[i] = row;
        aSrc[i] = Ap + (size_t)(rowBase + row) * K;
        int t8 = row >> 4, sub = (row >> 3) & 1;
        int wRow = colBase + (t8 << 3) + (row & 7);
        bSrc[i] = (sub ? Bu_ : Bg_) + (size_t)wRow * K;
    }
    int cOfs[4];
#pragma unroll
    for (int i = 0; i < 4; i++) cOfs[i] = ((tid + i * 256) & 7) * 4;

    float acc[4][4][4] = {};
    const int KT = K / BK;

    // prologue
#pragma unroll
    for (int pt = 0; pt < NSTG - 1; pt++) {
        float* dstA = smem + pt * STAGE_FLOATS;
        float* dstB = dstA + BM * BKP;
#pragma unroll
        for (int i = 0; i < 4; i++)
            cp_async16(smem_u32(dstA + sRow[i] * BKP + cOfs[i]),
                       aSrc[i] + pt * BK + cOfs[i]);
#pragma unroll
        for (int i = 0; i < 4; i++)
            cp_async16(smem_u32(dstB + sRow[i] * BKP + cOfs[i]),
                       bSrc[i] + pt * BK + cOfs[i]);
        asm volatile("cp.async.commit_group;" ::: "memory");
    }

    for (int kt = 0; kt < KT; kt++) {
        if (kt < KT - 1) cp_wait<1>();
        else             cp_wait<0>();
        __syncthreads();

        int lt = kt + NSTG - 1;
        if (lt < KT) {
            float* dstA = smem + (lt % NSTG) * STAGE_FLOATS;
            float* dstB = dstA + BM * BKP;
#pragma unroll
            for (int i = 0; i < 4; i++)
                cp_async16(smem_u32(dstA + sRow[i] * BKP + cOfs[i]),
                           aSrc[i] + lt * BK + cOfs[i]);
#pragma unroll
            for (int i = 0; i < 4; i++)
                cp_async16(smem_u32(dstB + sRow[i] * BKP + cOfs[i]),
                           bSrc[i] + lt * BK + cOfs[i]);
            asm volatile("cp.async.commit_group;" ::: "memory");
        }

        const float* As = smem + (kt % NSTG) * STAGE_FLOATS;
        const float* Bs = As + BM * BKP;
        uint32_t aBase = smem_u32(As + (wm * 64 + aRow) * BKP + aK);
        uint32_t bBase = smem_u32(Bs + (wn * 32 + bRow) * BKP + bK);

#pragma unroll
        for (int k8 = 0; k8 < BK / 8; k8++) {
            uint32_t kOfs = k8 * 8 * 4;
            uint32_t af[4][4], bf2[2][4];
#pragma unroll
            for (int mf = 0; mf < 4; mf++)
                ldsm_x4(af[mf][0], af[mf][1], af[mf][2], af[mf][3],
                        aBase + mf * (16 * BKP * 4) + kOfs);
#pragma unroll
            for (int pr = 0; pr < 2; pr++)
                ldsm_x4(bf2[pr][0], bf2[pr][1], bf2[pr][2], bf2[pr][3],
                        bBase + pr * (16 * BKP * 4) + kOfs);
#pragma unroll
            for (int mf = 0; mf < 4; mf++)
#pragma unroll
                for (int nf = 0; nf < 4; nf++) {
                    uint32_t b0 = bf2[nf >> 1][(nf & 1) * 2];
                    uint32_t b1 = bf2[nf >> 1][(nf & 1) * 2 + 1];
                    asm volatile(
                        "mma.sync.aligned.m16n8k8.row.col.f32.tf32.tf32.f32 "
                        "{%0,%1,%2,%3}, {%4,%5,%6,%7}, {%8,%9}, {%0,%1,%2,%3};"
                        : "+f"(acc[mf][nf][0]), "+f"(acc[mf][nf][1]),
                          "+f"(acc[mf][nf][2]), "+f"(acc[mf][nf][3])
                        : "r"(af[mf][0]), "r"(af[mf][1]),
                          "r"(af[mf][2]), "r"(af[mf][3]),
                          "r"(b0), "r"(b1));
                }
        }
    }

    // fused silu epilogue: nf even = gate, nf odd = up (same cols).
#pragma unroll
    for (int mf = 0; mf < 4; mf++) {
        int r0 = rowBase + wm * 64 + mf * 16 + grp;
#pragma unroll
        for (int pr = 0; pr < 2; pr++) {
            int tcg = 2 * wn + pr;                 // col-group within 64
            int col = colBase + tcg * 8 + tig * 2;
            float* ga = acc[mf][2 * pr];
            float* ua = acc[mf][2 * pr + 1];
            float2 v0 = { silu_mul_rna(ga[0], ua[0]), silu_mul_rna(ga[1], ua[1]) };
            float2 v1 = { silu_mul_rna(ga[2], ua[2]), silu_mul_rna(ga[3], ua[3]) };
            *(float2*)(Hp + (size_t)r0 * N + col) = v0;
            *(float2*)(Hp + (size_t)(r0 + 8) * N + col) = v1;
        }
    }
}

// ----------------- down GEMM body (generic) + merged launcher ---------------
__device__ __forceinline__ void gemm_body(
    const float* __restrict__ Ap, const float* __restrict__ Bp,
    float* __restrict__ Cp, int K, int N, int rowBase, int colBase,
    int mode, const float* __restrict__ rs, float* smem)
{
    int tid = threadIdx.x;
    int w = tid >> 5, lane = tid & 31;
    int wm = w >> 2, wn = w & 3;
    int grp = lane >> 2, tig = lane & 3;
    int q = lane >> 3, r8 = lane & 7;
    int aRow = (q & 1) * 8 + r8, aK = (q >> 1) * 4;
    int bRow = (q >> 1) * 8 + r8, bK = (q & 1) * 4;

    const float* Ag = Ap + (size_t)rowBase * K;
    const float* Bg = Bp + (size_t)colBase * K;

    float acc[4][4][4] = {};
    int KT = K / BK;

#pragma unroll
    for (int pt = 0; pt < NSTG - 1; pt++) {
        float* dstA = smem + pt * STAGE_FLOATS;
        float* dstB = dstA + BM * BKP;
#pragma unroll
        for (int i = 0; i < 4; i++) {
            int idx = tid + i * 256, row = idx >> 3, c = idx & 7;
            cp_async16(smem_u32(dstA + row * BKP + c * 4),
                       Ag + (size_t)row * K + pt * BK + c * 4);
        }
#pragma unroll
        for (int i = 0; i < 4; i++) {
            int idx = tid + i * 256, row = idx >> 3, c = idx & 7;
            cp_async16(smem_u32(dstB + row * BKP + c * 4),
                       Bg + (size_t)row * K + pt * BK + c * 4);
        }
        asm volatile("cp.async.commit_group;" ::: "memory");
    }

    for (int kt = 0; kt < KT; kt++) {
        if (kt < KT - 1) cp_wait<1>();
        else             cp_wait<0>();
        __syncthreads();

        int lt = kt + NSTG - 1;
        if (lt < KT) {
            float* dstA = smem + (lt % NSTG) * STAGE_FLOATS;
            float* dstB = dstA + BM * BKP;
#pragma unroll
            for (int i = 0; i < 4; i++) {
                int idx = tid + i * 256, row = idx >> 3, c = idx & 7;
                cp_async16(smem_u32(dstA + row * BKP + c * 4),
                           Ag + (size_t)row * K + lt * BK + c * 4);
            }
#pragma unroll
            for (int i = 0; i < 4; i++) {
                int idx = tid + i * 256, row = idx >> 3, c = idx & 7;
                cp_async16(smem_u32(dstB + row * BKP + c * 4),
                           Bg + (size_t)row * K + lt * BK + c * 4);
            }
            asm volatile("cp.async.commit_group;" ::: "memory");
        }

        const float* As = smem + (kt % NSTG) * STAGE_FLOATS;
        const float* Bs = As + BM * BKP;
        uint32_t aBase = smem_u32(As + (wm * 64 + aRow) * BKP + aK);
        uint32_t bBase = smem_u32(Bs + (wn * 32 + bRow) * BKP + bK);

#pragma unroll
        for (int k8 = 0; k8 < BK / 8; k8++) {
            uint32_t kOfs = k8 * 8 * 4;
            uint32_t af[4][4], bf2[2][4];
#pragma unroll
            for (int mf = 0; mf < 4; mf++)
                ldsm_x4(af[mf][0], af[mf][1], af[mf][2], af[mf][3],
                        aBase + mf * (16 * BKP * 4) + kOfs);
#pragma unroll
            for (int pr = 0; pr < 2; pr++)
                ldsm_x4(bf2[pr][0], bf2[pr][1], bf2[pr][2], bf2[pr][3],
                        bBase + pr * (16 * BKP * 4) + kOfs);
#pragma unroll
            for (int mf = 0; mf < 4; mf++)
#pragma unroll
                for (int nf = 0; nf < 4; nf++) {
                    uint32_t b0 = bf2[nf >> 1][(nf & 1) * 2];
                    uint32_t b1 = bf2[nf >> 1][(nf & 1) * 2 + 1];
                    asm volatile(
                        "mma.sync.aligned.m16n8k8.row.col.f32.tf32.tf32.f32 "
                        "{%0,%1,%2,%3}, {%4,%5,%6,%7}, {%8,%9}, {%0,%1,%2,%3};"
                        : "+f"(acc[mf][nf][0]), "+f"(acc[mf][nf][1]),
                          "+f"(acc[mf][nf][2]), "+f"(acc[mf][nf][3])
                        : "r"(af[mf][0]), "r"(af[mf][1]),
                          "r"(af[mf][2]), "r"(af[mf][3]),
                          "r"(b0), "r"(b1));
                }
        }
    }

#pragma unroll
    for (int mf = 0; mf < 4; mf++) {
        int r0 = rowBase + wm * 64 + mf * 16 + grp;
        float s0 = mode ? rs[r0] : 1.f;
        float s1 = mode ? rs[r0 + 8] : 1.f;
#pragma unroll
        for (int nf = 0; nf < 4; nf++) {
            int col = colBase + wn * 32 + nf * 8 + tig * 2;
            float2 v0 = { acc[mf][nf][0] * s0, acc[mf][nf][1] * s0 };
            float2 v1 = { acc[mf][nf][2] * s1, acc[mf][nf][3] * s1 };
            *(float2*)(Cp + (size_t)r0 * N + col) = v0;
            *(float2*)(Cp + (size_t)(r0 + 8) * N + col) = v1;
        }
    }
}

// flat grid: [0,256) shared down (K=IFX, rowscale), [256,576) dyn down (K=IDY)
__global__ __launch_bounds__(256, 2) void gemm_down_kernel(
    const float* __restrict__ hs, const float* __restrict__ sdw,
    float* __restrict__ outp, const float* __restrict__ wsh,
    const float* __restrict__ h, const float* __restrict__ ddw,
    float* __restrict__ y)
{
    extern __shared__ float smem[];
    int b = blockIdx.x;
    const float *Ap, *Bp; float* Cp; const float* rs; int K, mode, ty, tx;
    if (b < 256) {
        K = IFX; mode = 1; rs = wsh;
        ty = b >> 3; tx = b & 7;
        Ap = hs; Bp = sdw; Cp = outp;
    } else {
        K = IDY; mode = 0; rs = nullptr;
        int idx = b - 256;
        int e = idx / 40, t = idx - e * 40;
        ty = t >> 3; tx = t & 7;
        Ap = h + (size_t)e * CAPV * IDY;
        Bp = ddw + (size_t)e * HD * IDY;
        Cp = y + (size_t)e * CAPV * HD;
    }
    gemm_body(Ap, Bp, Cp, K, HD, ty * BM, tx * BN, mode, rs, smem);
}

// ----------------- combine dyn expert outputs into out ----------------------
__global__ __launch_bounds__(256) void combine_kernel(float* __restrict__ out)
{
    int t = blockIdx.x;
    int c = threadIdx.x;
    float4 acc = ((float4*)(out + (size_t)t * HD))[c];
#pragma unroll
    for (int k = 0; k < TOPK; k++) {
        int pos = d_tokpos[t * TOPK + k];
        if (pos >= 0) {
            int e = d_toke[t * TOPK + k];
            float w = d_tokw[t * TOPK + k];
            float4 v = ((const float4*)(d_ybuf + ((size_t)e * CAPV + pos) * HD))[c];
            acc.x += w * v.x; acc.y += w * v.y;
            acc.z += w * v.z; acc.w += w * v.w;
        }
    }
    ((float4*)(out + (size_t)t * HD))[c] = acc;
}

// ----------------- host launcher --------------------------------------------
extern "C" void kernel_launch(void* const* d_in, const int* in_sizes, int n_in,
                              void* d_out, int out_size)
{
    const float* x   = (const float*)d_in[0];
    const float* gw  = (const float*)d_in[1];
    const float* dgw = (const float*)d_in[2];
    const float* duw = (const float*)d_in[3];
    const float* ddw = (const float*)d_in[4];
    const float* sgw = (const float*)d_in[5];
    const float* suw = (const float*)d_in[6];
    const float* sdw = (const float*)d_in[7];
    float* out = (float*)d_out;

    float *p_xe, *p_h, *p_y, *p_hs, *p_wsh, *p_xr;
    float *p_dgw, *p_duw, *p_ddw, *p_sgw, *p_suw, *p_sdw;
    cudaGetSymbolAddress((void**)&p_xe, d_xe);
    cudaGetSymbolAddress((void**)&p_h, d_hbuf);
    cudaGetSymbolAddress((void**)&p_y, d_ybuf);
    cudaGetSymbolAddress((void**)&p_hs, d_hs);
    cudaGetSymbolAddress((void**)&p_wsh, d_wsh);
    cudaGetSymbolAddress((void**)&p_xr, d_xr);
    cudaGetSymbolAddress((void**)&p_dgw, d_dgw_r);
    cudaGetSymbolAddress((void**)&p_duw, d_duw_r);
    cudaGetSymbolAddress((void**)&p_ddw, d_ddw_r);
    cudaGetSymbolAddress((void**)&p_sgw, d_sgw_r);
    cudaGetSymbolAddress((void**)&p_suw, d_suw_r);
    cudaGetSymbolAddress((void**)&p_sdw, d_sdw_r);

    cudaFuncSetAttribute(gemm_gateup_fused,
                         cudaFuncAttributeMaxDynamicSharedMemorySize, GEMM_SMEM);
    cudaFuncSetAttribute(gemm_down_kernel,
                         cudaFuncAttributeMaxDynamicSharedMemorySize, GEMM_SMEM);

    // tf32 rounding prepass (one launch)
    round_all_kernel<<<(int)((ROUND_TOTAL + 255) / 256), 256>>>(
        (const float4*)dgw, (const float4*)duw, (const float4*)ddw,
        (const float4*)sgw, (const float4*)suw, (const float4*)sdw,
        (const float4*)x);

    // routing
    logits_kernel<<<(TT * NE + 7) / 8, 256>>>(x, gw);
    routing_kernel<<<(TT + 255) / 256, 256>>>();
    scan_kernel<<<EDN, 1024>>>();
    finalize_kernel<<<(TT + 255) / 256, 256>>>();
    gather_kernel<<<EDN * CAPV, 256>>>(x);

    // fused gate+up+silu GEMM (shared + dyn), then merged down GEMM
    gemm_gateup_fused<<<1344, 256, GEMM_SMEM>>>(
        p_xr, p_sgw, p_suw, p_hs, p_xe, p_dgw, p_duw, p_h);
    gemm_down_kernel<<<576, 256, GEMM_SMEM>>>(
        p_hs, p_sdw, out, p_wsh, p_h, p_ddw, p_y);

    // add dyn contributions
    combine_kernel<<<TT, 256>>>(out);
}